// round 1
// baseline (speedup 1.0000x reference)
#include <cuda_runtime.h>
#include <cuda_bf16.h>
#include <math.h>

#define BATCH 2
#define SEQ 2048
#define DIM 2048
#define NH 16
#define NKV 4
#define HD 128
#define MTOT (BATCH * SEQ)          // 4096

// ---------------- scratch (static device globals; no allocs allowed) ----------
__device__ float g_Q[(size_t)MTOT * DIM];        // 32 MB
__device__ float g_K[(size_t)MTOT * NKV * HD];   // 8 MB
__device__ float g_V[(size_t)MTOT * NKV * HD];   // 8 MB
__device__ float g_AO[(size_t)MTOT * DIM];       // 32 MB

// ---------------- SGEMM: C[M,N] = A[M,K] @ B[K,N], all row-major --------------
// 128x128 tile, BK=8, 256 threads, 8x8 per thread.
#define BM 128
#define BN 128
#define BK 8

__global__ __launch_bounds__(256) void sgemm_kernel(
    const float* __restrict__ A, const float* __restrict__ B,
    float* __restrict__ C, int M, int N, int K)
{
    __shared__ float As[BK][BM];
    __shared__ float Bs[BK][BN];

    const int tid = threadIdx.x;
    const int bm = blockIdx.y * BM;
    const int bn = blockIdx.x * BN;
    const int ty = tid >> 4;       // 0..15
    const int tx = tid & 15;       // 0..15

    // A tile load: 128x8 = 1024 floats; each thread one float4 along K
    const int arow = tid >> 1;            // 0..127
    const int acol = (tid & 1) * 4;       // 0 or 4
    // B tile load: 8x128; each thread one float4 along N
    const int brow = tid >> 5;            // 0..7
    const int bcol = (tid & 31) * 4;

    const float* Aptr = A + (size_t)(bm + arow) * K + acol;
    const float* Bptr = B + (size_t)brow * N + bn + bcol;

    float acc[8][8];
    #pragma unroll
    for (int i = 0; i < 8; i++)
        #pragma unroll
        for (int j = 0; j < 8; j++) acc[i][j] = 0.f;

    for (int k0 = 0; k0 < K; k0 += BK) {
        float4 a = *(const float4*)(Aptr + k0);
        As[acol + 0][arow] = a.x;
        As[acol + 1][arow] = a.y;
        As[acol + 2][arow] = a.z;
        As[acol + 3][arow] = a.w;
        *(float4*)&Bs[brow][bcol] = *(const float4*)(Bptr + (size_t)k0 * N);
        __syncthreads();

        #pragma unroll
        for (int k = 0; k < BK; k++) {
            float ra[8], rb[8];
            #pragma unroll
            for (int i = 0; i < 8; i++) ra[i] = As[k][ty * 8 + i];
            #pragma unroll
            for (int j = 0; j < 8; j++) rb[j] = Bs[k][tx * 8 + j];
            #pragma unroll
            for (int i = 0; i < 8; i++)
                #pragma unroll
                for (int j = 0; j < 8; j++)
                    acc[i][j] = fmaf(ra[i], rb[j], acc[i][j]);
        }
        __syncthreads();
    }

    #pragma unroll
    for (int i = 0; i < 8; i++) {
        float* Crow = C + (size_t)(bm + ty * 8 + i) * N + bn + tx * 8;
        #pragma unroll
        for (int j = 0; j < 8; j += 4) {
            float4 v = make_float4(acc[i][j], acc[i][j + 1], acc[i][j + 2], acc[i][j + 3]);
            *(float4*)(Crow + j) = v;
        }
    }
}

// ---------------- RoPE ------------------------------------------------------
// X: [B, S, heads*HD]; pairs (2i, 2i+1) within each head rotated by cos/sin[s, i]
__global__ void rope_kernel(float* __restrict__ X,
                            const float* __restrict__ cs,
                            const float* __restrict__ sn,
                            int heads)
{
    int idx = blockIdx.x * blockDim.x + threadIdx.x;
    int total = BATCH * SEQ * heads * (HD / 2);
    if (idx >= total) return;
    int i = idx & 63;                       // 0..63
    int h = (idx >> 6) % heads;
    int s = (idx / (64 * heads)) % SEQ;
    int b = idx / (64 * heads * SEQ);
    float c = cs[s * 64 + i];
    float ss = sn[s * 64 + i];
    float* p = X + ((size_t)(b * SEQ + s) * heads + h) * HD + 2 * i;
    float xr = p[0], xi = p[1];
    p[0] = xr * c - xi * ss;
    p[1] = xr * ss + xi * c;
}

// ---------------- Flash attention (causal, GQA) -----------------------------
// grid: (qtiles=32, NH=16, B=2), 256 threads.
// BLOCK_M = 64 query rows, BLOCK_N = 64 keys per iteration, HEAD_DIM = 128.
// Thread t: query row r = t/4, column-group cseg = t%4 (interleaved col owner),
// output cols [cseg*32, cseg*32+32).
#define FM 64
#define FN 64
#define QSTR 132   // padded row stride (floats) to avoid bank conflicts
#define SSTR 68

__global__ __launch_bounds__(256) void flash_kernel(
    const float* __restrict__ Q, const float* __restrict__ K,
    const float* __restrict__ V, float* __restrict__ O)
{
    extern __shared__ float sm[];
    float* Qs = sm;                      // FM * QSTR
    float* Ks = Qs + FM * QSTR;          // FM * QSTR
    float* Vs = Ks + FM * QSTR;          // FM * QSTR
    float* Ss = Vs + FM * QSTR;          // FM * SSTR

    const int qtile = blockIdx.x;
    const int h = blockIdx.y;
    const int b = blockIdx.z;
    const int g = h >> 2;                // kv head
    const int tid = threadIdx.x;
    const int r = tid >> 2;              // local query row
    const int cseg = tid & 3;
    const int m_base = qtile * FM;
    const float scale = 0.08838834764831845f;  // 1/sqrt(128)

    // load Q tile (64 x 128)
    for (int t = tid; t < FM * HD / 4; t += 256) {
        int row = t >> 5;
        int col = (t & 31) * 4;
        *(float4*)(Qs + row * QSTR + col) =
            *(const float4*)(Q + (size_t)(b * SEQ + m_base + row) * DIM + h * HD + col);
    }

    float m_run = -1e30f, l_run = 0.f;
    float acc[32];
    #pragma unroll
    for (int j = 0; j < 32; j++) acc[j] = 0.f;

    for (int ntile = 0; ntile <= qtile; ntile++) {
        const int n_base = ntile * FN;
        __syncthreads();   // protect Ks/Vs reuse (and Q on first iter)
        for (int t = tid; t < FN * HD / 4; t += 256) {
            int row = t >> 5;
            int col = (t & 31) * 4;
            size_t src = (size_t)(b * SEQ + n_base + row) * (NKV * HD) + g * HD + col;
            *(float4*)(Ks + row * QSTR + col) = *(const float4*)(K + src);
            *(float4*)(Vs + row * QSTR + col) = *(const float4*)(V + src);
        }
        __syncthreads();

        // S = Q @ K^T for row r, interleaved cols (cseg + 4*c)
        float sv[16];
        #pragma unroll
        for (int c = 0; c < 16; c++) sv[c] = 0.f;
        for (int d = 0; d < HD; d += 4) {
            float4 q = *(float4*)(Qs + r * QSTR + d);
            #pragma unroll
            for (int c = 0; c < 16; c++) {
                float4 k = *(float4*)(Ks + (cseg + 4 * c) * QSTR + d);
                sv[c] += q.x * k.x + q.y * k.y + q.z * k.z + q.w * k.w;
            }
        }

        // mask + scale + tile max
        float tmax = -1e30f;
        #pragma unroll
        for (int c = 0; c < 16; c++) {
            int kg = n_base + cseg + 4 * c;
            float val = (kg <= m_base + r) ? sv[c] * scale : -1e30f;
            sv[c] = val;
            tmax = fmaxf(tmax, val);
        }
        tmax = fmaxf(tmax, __shfl_xor_sync(0xffffffffu, tmax, 1));
        tmax = fmaxf(tmax, __shfl_xor_sync(0xffffffffu, tmax, 2));

        float m_new = fmaxf(m_run, tmax);
        float alpha = __expf(m_run - m_new);
        float lsum = 0.f;
        #pragma unroll
        for (int c = 0; c < 16; c++) {
            float p = __expf(sv[c] - m_new);
            Ss[r * SSTR + cseg + 4 * c] = p;
            lsum += p;
        }
        lsum += __shfl_xor_sync(0xffffffffu, lsum, 1);
        lsum += __shfl_xor_sync(0xffffffffu, lsum, 2);
        l_run = l_run * alpha + lsum;
        m_run = m_new;
        #pragma unroll
        for (int j = 0; j < 32; j++) acc[j] *= alpha;
        __syncwarp();

        // O += P @ V  (cols cseg*32 .. +32)
        for (int k = 0; k < FN; k++) {
            float p = Ss[r * SSTR + k];
            #pragma unroll
            for (int j = 0; j < 32; j += 4) {
                float4 v = *(float4*)(Vs + k * QSTR + cseg * 32 + j);
                acc[j]     = fmaf(p, v.x, acc[j]);
                acc[j + 1] = fmaf(p, v.y, acc[j + 1]);
                acc[j + 2] = fmaf(p, v.z, acc[j + 2]);
                acc[j + 3] = fmaf(p, v.w, acc[j + 3]);
            }
        }
    }

    float inv_l = 1.f / l_run;
    float* orow = O + (size_t)(b * SEQ + m_base + r) * DIM + h * HD + cseg * 32;
    #pragma unroll
    for (int j = 0; j < 32; j += 4) {
        float4 v = make_float4(acc[j] * inv_l, acc[j + 1] * inv_l,
                               acc[j + 2] * inv_l, acc[j + 3] * inv_l);
        *(float4*)(orow + j) = v;
    }
}

// ---------------- launch -----------------------------------------------------
extern "C" void kernel_launch(void* const* d_in, const int* in_sizes, int n_in,
                              void* d_out, int out_size)
{
    const float* x  = (const float*)d_in[0];
    const float* fc = (const float*)d_in[1];
    const float* fs = (const float*)d_in[2];
    const float* Wq = (const float*)d_in[3];
    const float* Wk = (const float*)d_in[4];
    const float* Wv = (const float*)d_in[5];
    const float* Wo = (const float*)d_in[6];
    float* out = (float*)d_out;

    float *Q, *Kp, *Vp, *AO;
    cudaGetSymbolAddress((void**)&Q,  g_Q);
    cudaGetSymbolAddress((void**)&Kp, g_K);
    cudaGetSymbolAddress((void**)&Vp, g_V);
    cudaGetSymbolAddress((void**)&AO, g_AO);

    // projections
    sgemm_kernel<<<dim3(DIM / BN, MTOT / BM), 256>>>(x, Wq, Q, MTOT, DIM, DIM);
    sgemm_kernel<<<dim3((NKV * HD) / BN, MTOT / BM), 256>>>(x, Wk, Kp, MTOT, NKV * HD, DIM);
    sgemm_kernel<<<dim3((NKV * HD) / BN, MTOT / BM), 256>>>(x, Wv, Vp, MTOT, NKV * HD, DIM);

    // RoPE
    {
        int nq = BATCH * SEQ * NH * (HD / 2);
        rope_kernel<<<(nq + 255) / 256, 256>>>(Q, fc, fs, NH);
        int nk = BATCH * SEQ * NKV * (HD / 2);
        rope_kernel<<<(nk + 255) / 256, 256>>>(Kp, fc, fs, NKV);
    }

    // flash attention
    {
        const int smem = (3 * FM * QSTR + FM * SSTR) * (int)sizeof(float); // 118784 B
        cudaFuncSetAttribute(flash_kernel, cudaFuncAttributeMaxDynamicSharedMemorySize, smem);
        flash_kernel<<<dim3(SEQ / FM, NH, BATCH), 256, smem>>>(Q, Kp, Vp, AO);
    }

    // output projection
    sgemm_kernel<<<dim3(DIM / BN, MTOT / BM), 256>>>(AO, Wo, out, MTOT, DIM, DIM);
}

// round 3
// speedup vs baseline: 6.1396x; 6.1396x over previous
#include <cuda_runtime.h>
#include <cuda_bf16.h>
#include <cuda_fp16.h>
#include <math.h>
#include <stdint.h>

#define BATCH 2
#define SEQ 2048
#define DIM 2048
#define NH 16
#define NKV 4
#define HD 128
#define MTOT (BATCH * SEQ)          // 4096
#define KVD (NKV * HD)              // 512
#define KP (3 * DIM)                // 6144 split-K
#define KPB (KP * 2)                // bytes per split row

// ---------------- scratch (static device globals; no allocs allowed) ----------
__device__ float g_Q[(size_t)MTOT * DIM];
__device__ float g_K[(size_t)MTOT * KVD];
__device__ float g_V[(size_t)MTOT * KVD];
__device__ float g_AO[(size_t)MTOT * DIM];
__device__ __nv_bfloat16 g_As [(size_t)MTOT * KP];
__device__ __nv_bfloat16 g_WqT[(size_t)DIM  * KP];
__device__ __nv_bfloat16 g_WkT[(size_t)KVD  * KP];
__device__ __nv_bfloat16 g_WvT[(size_t)KVD  * KP];
__device__ __nv_bfloat16 g_WoT[(size_t)DIM  * KP];
__device__ __half g_Qh[(size_t)MTOT * DIM];
__device__ __half g_Kh[(size_t)MTOT * KVD];
__device__ __half g_Vh[(size_t)MTOT * KVD];

// ======================= small PTX helpers ===================================
__device__ __forceinline__ uint32_t smem_u32(const void* p) {
    uint32_t a;
    asm("{ .reg .u64 t; cvta.to.shared.u64 t, %1; cvt.u32.u64 %0, t; }" : "=r"(a) : "l"(p));
    return a;
}
__device__ __forceinline__ void cp16(uint32_t dst, const void* src) {
    asm volatile("cp.async.cg.shared.global [%0], [%1], 16;" :: "r"(dst), "l"(src));
}
__device__ __forceinline__ void cp_commit() { asm volatile("cp.async.commit_group;"); }
template <int N> __device__ __forceinline__ void cp_wait() {
    asm volatile("cp.async.wait_group %0;" :: "n"(N));
}
__device__ __forceinline__ void ldmx4(uint32_t* r, uint32_t a) {
    asm volatile("ldmatrix.sync.aligned.m8n8.x4.shared.b16 {%0,%1,%2,%3}, [%4];"
                 : "=r"(r[0]), "=r"(r[1]), "=r"(r[2]), "=r"(r[3]) : "r"(a));
}
__device__ __forceinline__ void ldmx4t(uint32_t* r, uint32_t a) {
    asm volatile("ldmatrix.sync.aligned.m8n8.x4.trans.shared.b16 {%0,%1,%2,%3}, [%4];"
                 : "=r"(r[0]), "=r"(r[1]), "=r"(r[2]), "=r"(r[3]) : "r"(a));
}
__device__ __forceinline__ void mma_bf16(float* c, const uint32_t* a, uint32_t b0, uint32_t b1) {
    asm volatile("mma.sync.aligned.m16n8k16.row.col.f32.bf16.bf16.f32 "
                 "{%0,%1,%2,%3},{%4,%5,%6,%7},{%8,%9},{%0,%1,%2,%3};"
                 : "+f"(c[0]), "+f"(c[1]), "+f"(c[2]), "+f"(c[3])
                 : "r"(a[0]), "r"(a[1]), "r"(a[2]), "r"(a[3]), "r"(b0), "r"(b1));
}
__device__ __forceinline__ void mma_f16(float* c, const uint32_t* a, uint32_t b0, uint32_t b1) {
    asm volatile("mma.sync.aligned.m16n8k16.row.col.f32.f16.f16.f32 "
                 "{%0,%1,%2,%3},{%4,%5,%6,%7},{%8,%9},{%0,%1,%2,%3};"
                 : "+f"(c[0]), "+f"(c[1]), "+f"(c[2]), "+f"(c[3])
                 : "r"(a[0]), "r"(a[1]), "r"(a[2]), "r"(a[3]), "r"(b0), "r"(b1));
}
__device__ __forceinline__ uint32_t h2_u32(__half2 h) {
    return *reinterpret_cast<uint32_t*>(&h);
}

// ======================= split / transpose conversions =======================
__global__ void split_a_kernel(const float* __restrict__ A, __nv_bfloat16* __restrict__ out,
                               int M, int K)
{
    int i = blockIdx.x * blockDim.x + threadIdx.x;
    if (i >= M * K) return;
    int r = i / K, c = i % K;
    float a = A[i];
    __nv_bfloat16 hi = __float2bfloat16(a);
    __nv_bfloat16 lo = __float2bfloat16(a - __bfloat162float(hi));
    size_t o = (size_t)r * (3 * K) + c;
    out[o] = hi; out[o + K] = lo; out[o + 2 * K] = hi;
}

// W [K, N] fp32 -> out [N, 3K] bf16 : [hi | hi | lo]
__global__ void split_wt_kernel(const float* __restrict__ W, __nv_bfloat16* __restrict__ out,
                                int K, int N)
{
    __shared__ float t[32][33];
    int k0 = blockIdx.y * 32, n0 = blockIdx.x * 32;
    int tx = threadIdx.x, ty = threadIdx.y;   // 32 x 8
    #pragma unroll
    for (int i = 0; i < 32; i += 8)
        t[ty + i][tx] = W[(size_t)(k0 + ty + i) * N + n0 + tx];
    __syncthreads();
    #pragma unroll
    for (int i = 0; i < 32; i += 8) {
        int n = n0 + ty + i, k = k0 + tx;
        float a = t[tx][ty + i];
        __nv_bfloat16 hi = __float2bfloat16(a);
        __nv_bfloat16 lo = __float2bfloat16(a - __bfloat162float(hi));
        size_t o = (size_t)n * (3 * K) + k;
        out[o] = hi; out[o + K] = hi; out[o + 2 * K] = lo;
    }
}

// ======================= bf16 mma.sync GEMM ==================================
// C[M, Ntot] = A'[M, KP] @ B'[Ntot, KP]^T.  CTA tile 128x128, BK=32 elems.
// 8 warps as 2(m) x 4(n); each warp 64m x 32n via m16n8k16.
#define GSTRB 80                       // smem row stride bytes (64B data + 16B pad)
#define GSTAGE 20480                   // (128 + 128) rows * 80B
#define GNIT (KP / 32)                 // 192

__global__ __launch_bounds__(256) void gemm_bf16_kernel(
    const __nv_bfloat16* __restrict__ A, const __nv_bfloat16* __restrict__ B,
    float* __restrict__ C, int Ntot)
{
    __shared__ __align__(16) char smbuf[2 * GSTAGE];
    const uint32_t smBase = smem_u32(smbuf);

    const int tid = threadIdx.x;
    const int lane = tid & 31;
    const int wid = tid >> 5;
    const int wm = wid >> 2, wn = wid & 3;
    const int m0 = blockIdx.y * 128;
    const int n0 = blockIdx.x * 128;

    const uint32_t offA = ((((lane >> 3) & 1) * 8 + (lane & 7)) * GSTRB) + ((lane >> 4) * 16);
    const uint32_t offB = (((lane >> 4) * 8 + (lane & 7)) * GSTRB) + (((lane >> 3) & 1) * 16);

    const char* Ab = (const char*)A;
    const char* Bb = (const char*)B;

    const int lrow = tid >> 2;          // 0..63
    const int lcol = tid & 3;           // 0..3

    auto load_stage = [&](int it_k, int s) {
        uint32_t base = smBase + s * GSTAGE;
        int kb = it_k * 64;
        #pragma unroll
        for (int half = 0; half < 2; half++) {       // A rows 0-63, 64-127
            int row = lrow + half * 64;
            cp16(base + row * GSTRB + lcol * 16,
                 Ab + (size_t)(m0 + row) * KPB + kb + lcol * 16);
        }
        #pragma unroll
        for (int half = 0; half < 2; half++) {       // B rows
            int row = lrow + half * 64;
            cp16(base + 10240 + row * GSTRB + lcol * 16,
                 Bb + (size_t)(n0 + row) * KPB + kb + lcol * 16);
        }
        cp_commit();
    };

    float acc[4][4][4];
    #pragma unroll
    for (int i = 0; i < 4; i++)
        #pragma unroll
        for (int j = 0; j < 4; j++)
            #pragma unroll
            for (int k = 0; k < 4; k++) acc[i][j][k] = 0.f;

    load_stage(0, 0);

    for (int i = 0; i < GNIT; i++) {
        if (i + 1 < GNIT) { load_stage(i + 1, (i + 1) & 1); cp_wait<1>(); }
        else cp_wait<0>();
        __syncthreads();

        uint32_t sA = smBase + (i & 1) * GSTAGE;
        uint32_t sB = sA + 10240;
        #pragma unroll
        for (int ks = 0; ks < 2; ks++) {
            uint32_t afr[4][4], bfr[2][4];
            #pragma unroll
            for (int mt = 0; mt < 4; mt++)
                ldmx4(afr[mt], sA + (wm * 64 + mt * 16) * GSTRB + ks * 32 + offA);
            #pragma unroll
            for (int nt2 = 0; nt2 < 2; nt2++)
                ldmx4(bfr[nt2], sB + (wn * 32 + nt2 * 16) * GSTRB + ks * 32 + offB);
            #pragma unroll
            for (int mt = 0; mt < 4; mt++)
                #pragma unroll
                for (int nt = 0; nt < 4; nt++)
                    mma_bf16(acc[mt][nt], afr[mt], bfr[nt >> 1][(nt & 1) * 2],
                             bfr[nt >> 1][(nt & 1) * 2 + 1]);
        }
        __syncthreads();
    }

    // epilogue
    #pragma unroll
    for (int mt = 0; mt < 4; mt++) {
        int r0 = m0 + wm * 64 + mt * 16 + (lane >> 2);
        #pragma unroll
        for (int nt = 0; nt < 4; nt++) {
            int col = n0 + wn * 32 + nt * 8 + (lane & 3) * 2;
            float2 v0 = make_float2(acc[mt][nt][0], acc[mt][nt][1]);
            float2 v1 = make_float2(acc[mt][nt][2], acc[mt][nt][3]);
            *(float2*)(C + (size_t)r0 * Ntot + col) = v0;
            *(float2*)(C + (size_t)(r0 + 8) * Ntot + col) = v1;
        }
    }
}

// ---------------- RoPE + fp16 convert ----------------------------------------
// X fp32 [B,S,heads*HD] -> Xh fp16 (rotated, optionally pre-scaled)
__global__ void rope_cvt_kernel(const float* __restrict__ X, __half* __restrict__ Xh,
                                const float* __restrict__ cs, const float* __restrict__ sn,
                                int heads, float mul)
{
    int idx = blockIdx.x * blockDim.x + threadIdx.x;
    int total = BATCH * SEQ * heads * (HD / 2);
    if (idx >= total) return;
    int i = idx & 63;
    int h = (idx >> 6) % heads;
    int s = (idx / (64 * heads)) % SEQ;
    int b = idx / (64 * heads * SEQ);
    float c = cs[s * 64 + i];
    float ss = sn[s * 64 + i];
    size_t off = ((size_t)(b * SEQ + s) * heads + h) * HD + 2 * i;
    const float* p = X + off;
    float xr = p[0], xi = p[1];
    float orr = (xr * c - xi * ss) * mul;
    float oii = (xr * ss + xi * c) * mul;
    *(__half2*)(Xh + off) = __floats2half2_rn(orr, oii);
}

__global__ void cvt_h_kernel(const float* __restrict__ X, __half* __restrict__ Xh, int n2)
{
    int i = blockIdx.x * blockDim.x + threadIdx.x;
    if (i >= n2) return;
    float2 v = *(const float2*)(X + 2 * i);
    *(__half2*)(Xh + 2 * i) = __floats2half2_rn(v.x, v.y);
}

// ---------------- Flash attention (fp16 mma.sync, causal, GQA) ---------------
// grid (SEQ/64, NH, BATCH), 128 threads (4 warps; warp w owns rows w*16..w*16+15).
#define FSTR 272                      // smem row stride bytes (256B data + 16B pad)
#define FTILE (64 * FSTR)             // 17408
#define FSMEM (3 * FTILE)             // 52224 (dynamic)

__global__ __launch_bounds__(128) void flash_mma_kernel(
    const __half* __restrict__ Q, const __half* __restrict__ K,
    const __half* __restrict__ V, float* __restrict__ O)
{
    extern __shared__ char fsm[];
    const uint32_t smQ = smem_u32(fsm);
    const uint32_t smK = smQ + FTILE;
    const uint32_t smV = smK + FTILE;

    const int tid = threadIdx.x;
    const int lane = tid & 31;
    const int wid = tid >> 5;
    const int qtile = blockIdx.x, h = blockIdx.y, b = blockIdx.z;
    const int g = h >> 2;
    const int m_base = qtile * 64;

    const uint32_t offQ = ((((lane >> 3) & 1) * 8 + (lane & 7)) * FSTR) + ((lane >> 4) * 16);
    const uint32_t offK = (((lane >> 4) * 8 + (lane & 7)) * FSTR) + (((lane >> 3) & 1) * 16);

    const char* Qb = (const char*)Q;
    const char* Kb = (const char*)K;
    const char* Vb = (const char*)V;

    // load Q tile (64 x 128 fp16)
    #pragma unroll
    for (int it = 0; it < 8; it++) {
        int c = it * 128 + tid;
        int row = c >> 4, col = c & 15;
        cp16(smQ + row * FSTR + col * 16,
             Qb + ((size_t)(b * SEQ + m_base + row) * DIM + h * HD) * 2 + col * 16);
    }
    cp_commit(); cp_wait<0>();
    __syncthreads();

    uint32_t qfr[8][4];
    #pragma unroll
    for (int kd = 0; kd < 8; kd++)
        ldmx4(qfr[kd], smQ + (wid * 16) * FSTR + kd * 32 + offQ);

    float acc[16][4];
    #pragma unroll
    for (int i = 0; i < 16; i++)
        #pragma unroll
        for (int j = 0; j < 4; j++) acc[i][j] = 0.f;
    float mr0 = -1e30f, mr1 = -1e30f, l0 = 0.f, l1 = 0.f;

    for (int nt = 0; nt <= qtile; nt++) {
        __syncthreads();
        #pragma unroll
        for (int it = 0; it < 16; it++) {
            int c = it * 128 + tid;
            int which = c >> 10;
            int row = (c >> 4) & 63, col = c & 15;
            uint32_t dst = (which ? smV : smK) + row * FSTR + col * 16;
            const char* srcb = which ? Vb : Kb;
            cp16(dst, srcb + ((size_t)(b * SEQ + nt * 64 + row) * KVD + g * HD) * 2 + col * 16);
        }
        cp_commit(); cp_wait<0>();
        __syncthreads();

        // S = Q @ K^T (scaled+log2e folded into Q)
        float s[8][4];
        #pragma unroll
        for (int i = 0; i < 8; i++)
            #pragma unroll
            for (int j = 0; j < 4; j++) s[i][j] = 0.f;
        #pragma unroll
        for (int kd = 0; kd < 8; kd++) {
            #pragma unroll
            for (int nt2 = 0; nt2 < 4; nt2++) {
                uint32_t bfr[4];
                ldmx4(bfr, smK + nt2 * 16 * FSTR + kd * 32 + offK);
                mma_f16(s[2 * nt2],     qfr[kd], bfr[0], bfr[1]);
                mma_f16(s[2 * nt2 + 1], qfr[kd], bfr[2], bfr[3]);
            }
        }

        // causal mask (diagonal tile only)
        if (nt == qtile) {
            int rl0 = wid * 16 + (lane >> 2);
            int rl1 = rl0 + 8;
            #pragma unroll
            for (int kt = 0; kt < 8; kt++) {
                int cl = kt * 8 + (lane & 3) * 2;
                if (cl     > rl0) s[kt][0] = -1e30f;
                if (cl + 1 > rl0) s[kt][1] = -1e30f;
                if (cl     > rl1) s[kt][2] = -1e30f;
                if (cl + 1 > rl1) s[kt][3] = -1e30f;
            }
        }

        // row max
        float t0 = -1e30f, t1 = -1e30f;
        #pragma unroll
        for (int kt = 0; kt < 8; kt++) {
            t0 = fmaxf(t0, fmaxf(s[kt][0], s[kt][1]));
            t1 = fmaxf(t1, fmaxf(s[kt][2], s[kt][3]));
        }
        t0 = fmaxf(t0, __shfl_xor_sync(0xffffffffu, t0, 1));
        t0 = fmaxf(t0, __shfl_xor_sync(0xffffffffu, t0, 2));
        t1 = fmaxf(t1, __shfl_xor_sync(0xffffffffu, t1, 1));
        t1 = fmaxf(t1, __shfl_xor_sync(0xffffffffu, t1, 2));

        float mn0 = fmaxf(mr0, t0), mn1 = fmaxf(mr1, t1);
        float a0 = exp2f(mr0 - mn0), a1 = exp2f(mr1 - mn1);
        mr0 = mn0; mr1 = mn1;

        // probs (fp16, exp2 domain) + partial sums
        uint32_t pa[8][2];
        float lt0 = 0.f, lt1 = 0.f;
        #pragma unroll
        for (int kt = 0; kt < 8; kt++) {
            __half2 hp0 = h2exp2(__floats2half2_rn(s[kt][0] - mn0, s[kt][1] - mn0));
            __half2 hp1 = h2exp2(__floats2half2_rn(s[kt][2] - mn1, s[kt][3] - mn1));
            pa[kt][0] = h2_u32(hp0);
            pa[kt][1] = h2_u32(hp1);
            float2 f0 = __half22float2(hp0);
            float2 f1 = __half22float2(hp1);
            lt0 += f0.x + f0.y;
            lt1 += f1.x + f1.y;
        }
        lt0 += __shfl_xor_sync(0xffffffffu, lt0, 1);
        lt0 += __shfl_xor_sync(0xffffffffu, lt0, 2);
        lt1 += __shfl_xor_sync(0xffffffffu, lt1, 1);
        lt1 += __shfl_xor_sync(0xffffffffu, lt1, 2);
        l0 = l0 * a0 + lt0;
        l1 = l1 * a1 + lt1;

        // rescale accumulators
        #pragma unroll
        for (int i = 0; i < 16; i++) {
            acc[i][0] *= a0; acc[i][1] *= a0;
            acc[i][2] *= a1; acc[i][3] *= a1;
        }

        // O += P @ V
        #pragma unroll
        for (int kt2 = 0; kt2 < 4; kt2++) {
            uint32_t pfr[4] = { pa[2 * kt2][0], pa[2 * kt2][1],
                                pa[2 * kt2 + 1][0], pa[2 * kt2 + 1][1] };
            #pragma unroll
            for (int dp = 0; dp < 8; dp++) {
                uint32_t vfr[4];
                ldmx4t(vfr, smV + kt2 * 16 * FSTR + dp * 32 + offQ);
                mma_f16(acc[2 * dp],     pfr, vfr[0], vfr[1]);
                mma_f16(acc[2 * dp + 1], pfr, vfr[2], vfr[3]);
            }
        }
    }

    float inv0 = 1.f / l0, inv1 = 1.f / l1;
    int r0 = m_base + wid * 16 + (lane >> 2);
    #pragma unroll
    for (int ntl = 0; ntl < 16; ntl++) {
        int col = h * HD + ntl * 8 + (lane & 3) * 2;
        size_t tok0 = (size_t)(b * SEQ + r0) * DIM + col;
        size_t tok1 = (size_t)(b * SEQ + r0 + 8) * DIM + col;
        *(float2*)(O + tok0) = make_float2(acc[ntl][0] * inv0, acc[ntl][1] * inv0);
        *(float2*)(O + tok1) = make_float2(acc[ntl][2] * inv1, acc[ntl][3] * inv1);
    }
}

// ---------------- launch -----------------------------------------------------
extern "C" void kernel_launch(void* const* d_in, const int* in_sizes, int n_in,
                              void* d_out, int out_size)
{
    const float* x  = (const float*)d_in[0];
    const float* fc = (const float*)d_in[1];
    const float* fs = (const float*)d_in[2];
    const float* Wq = (const float*)d_in[3];
    const float* Wk = (const float*)d_in[4];
    const float* Wv = (const float*)d_in[5];
    const float* Wo = (const float*)d_in[6];
    float* out = (float*)d_out;

    float *Q, *Kp, *Vp, *AO;
    __nv_bfloat16 *As, *WqT, *WkT, *WvT, *WoT;
    __half *Qh, *Kh, *Vh;
    cudaGetSymbolAddress((void**)&Q,  g_Q);
    cudaGetSymbolAddress((void**)&Kp, g_K);
    cudaGetSymbolAddress((void**)&Vp, g_V);
    cudaGetSymbolAddress((void**)&AO, g_AO);
    cudaGetSymbolAddress((void**)&As,  g_As);
    cudaGetSymbolAddress((void**)&WqT, g_WqT);
    cudaGetSymbolAddress((void**)&WkT, g_WkT);
    cudaGetSymbolAddress((void**)&WvT, g_WvT);
    cudaGetSymbolAddress((void**)&WoT, g_WoT);
    cudaGetSymbolAddress((void**)&Qh, g_Qh);
    cudaGetSymbolAddress((void**)&Kh, g_Kh);
    cudaGetSymbolAddress((void**)&Vh, g_Vh);

    // splits
    {
        int n = MTOT * DIM;
        split_a_kernel<<<(n + 255) / 256, 256>>>(x, As, MTOT, DIM);
        split_wt_kernel<<<dim3(DIM / 32, DIM / 32), dim3(32, 8)>>>(Wq, WqT, DIM, DIM);
        split_wt_kernel<<<dim3(KVD / 32, DIM / 32), dim3(32, 8)>>>(Wk, WkT, DIM, KVD);
        split_wt_kernel<<<dim3(KVD / 32, DIM / 32), dim3(32, 8)>>>(Wv, WvT, DIM, KVD);
        split_wt_kernel<<<dim3(DIM / 32, DIM / 32), dim3(32, 8)>>>(Wo, WoT, DIM, DIM);
    }

    // projections (bf16 mma.sync, split-K accuracy)
    gemm_bf16_kernel<<<dim3(DIM / 128, MTOT / 128), 256>>>(As, WqT, Q, DIM);
    gemm_bf16_kernel<<<dim3(KVD / 128, MTOT / 128), 256>>>(As, WkT, Kp, KVD);
    gemm_bf16_kernel<<<dim3(KVD / 128, MTOT / 128), 256>>>(As, WvT, Vp, KVD);

    // RoPE + fp16 conversion; fold softmax scale*log2(e) into Q
    {
        const float qmul = 0.08838834764831845f * 1.4426950408889634f;
        int nq = BATCH * SEQ * NH * (HD / 2);
        rope_cvt_kernel<<<(nq + 255) / 256, 256>>>(Q, Qh, fc, fs, NH, qmul);
        int nk = BATCH * SEQ * NKV * (HD / 2);
        rope_cvt_kernel<<<(nk + 255) / 256, 256>>>(Kp, Kh, fc, fs, NKV, 1.0f);
        int nv = MTOT * KVD / 2;
        cvt_h_kernel<<<(nv + 255) / 256, 256>>>(Vp, Vh, nv);
    }

    // flash attention (fp16 tensor cores)
    {
        cudaFuncSetAttribute(flash_mma_kernel, cudaFuncAttributeMaxDynamicSharedMemorySize, FSMEM);
        flash_mma_kernel<<<dim3(SEQ / 64, NH, BATCH), 128, FSMEM>>>(Qh, Kh, Vh, AO);
    }

    // output projection
    {
        int n = MTOT * DIM;
        split_a_kernel<<<(n + 255) / 256, 256>>>(AO, As, MTOT, DIM);
        gemm_bf16_kernel<<<dim3(DIM / 128, MTOT / 128), 256>>>(As, WoT, out, DIM);
    }
}

// round 4
// speedup vs baseline: 9.0803x; 1.4790x over previous
#include <cuda_runtime.h>
#include <cuda_bf16.h>
#include <cuda_fp16.h>
#include <math.h>
#include <stdint.h>

#define BATCH 2
#define SEQ 2048
#define DIM 2048
#define NH 16
#define NKV 4
#define HD 128
#define MTOT (BATCH * SEQ)          // 4096
#define KVD (NKV * HD)              // 512
#define NQKV (DIM + 2 * KVD)        // 3072 fused QKV output cols
#define KP2 (2 * DIM)               // 4096 split-K (2-term)
#define KPB2 (KP2 * 2)              // bytes per split row

// ---------------- scratch (static device globals) ----------------------------
__device__ __half g_Ah  [(size_t)MTOT * KP2];   // activations split [hi|lo] (x, then attn-out)
__device__ __half g_Wqkv[(size_t)NQKV * KP2];   // [WqT;WkT;WvT] split [hi|hi]
__device__ __half g_Wo2 [(size_t)DIM  * KP2];   // WoT split [hi|hi]
__device__ __half g_Qh  [(size_t)MTOT * DIM];
__device__ __half g_Kh  [(size_t)MTOT * KVD];
__device__ __half g_Vh  [(size_t)MTOT * KVD];

#define QMUL (0.08838834764831845f * 1.4426950408889634f)   // scale * log2(e)

// ======================= small PTX helpers ===================================
__device__ __forceinline__ uint32_t smem_u32(const void* p) {
    uint32_t a;
    asm("{ .reg .u64 t; cvta.to.shared.u64 t, %1; cvt.u32.u64 %0, t; }" : "=r"(a) : "l"(p));
    return a;
}
__device__ __forceinline__ void cp16(uint32_t dst, const void* src) {
    asm volatile("cp.async.cg.shared.global [%0], [%1], 16;" :: "r"(dst), "l"(src));
}
__device__ __forceinline__ void cp_commit() { asm volatile("cp.async.commit_group;"); }
template <int N> __device__ __forceinline__ void cp_wait() {
    asm volatile("cp.async.wait_group %0;" :: "n"(N));
}
__device__ __forceinline__ void ldmx4(uint32_t* r, uint32_t a) {
    asm volatile("ldmatrix.sync.aligned.m8n8.x4.shared.b16 {%0,%1,%2,%3}, [%4];"
                 : "=r"(r[0]), "=r"(r[1]), "=r"(r[2]), "=r"(r[3]) : "r"(a));
}
__device__ __forceinline__ void ldmx4t(uint32_t* r, uint32_t a) {
    asm volatile("ldmatrix.sync.aligned.m8n8.x4.trans.shared.b16 {%0,%1,%2,%3}, [%4];"
                 : "=r"(r[0]), "=r"(r[1]), "=r"(r[2]), "=r"(r[3]) : "r"(a));
}
__device__ __forceinline__ void mma_f16(float* c, const uint32_t* a, uint32_t b0, uint32_t b1) {
    asm volatile("mma.sync.aligned.m16n8k16.row.col.f32.f16.f16.f32 "
                 "{%0,%1,%2,%3},{%4,%5,%6,%7},{%8,%9},{%0,%1,%2,%3};"
                 : "+f"(c[0]), "+f"(c[1]), "+f"(c[2]), "+f"(c[3])
                 : "r"(a[0]), "r"(a[1]), "r"(a[2]), "r"(a[3]), "r"(b0), "r"(b1));
}
__device__ __forceinline__ uint32_t h2_u32(__half2 h) {
    return *reinterpret_cast<uint32_t*>(&h);
}

// ======================= split conversions ===================================
// x [M,K] fp32 -> out [M, 2K] fp16 : [hi | lo]
__global__ void split_x_kernel(const float* __restrict__ A, __half* __restrict__ out,
                               int M, int K)
{
    int i = blockIdx.x * blockDim.x + threadIdx.x;
    int tot = M * (K / 2);
    if (i >= tot) return;
    int r = i / (K / 2), c = (i % (K / 2)) * 2;
    float2 v = *(const float2*)(A + (size_t)r * K + c);
    __half h0 = __float2half_rn(v.x), h1 = __float2half_rn(v.y);
    __half l0 = __float2half_rn(v.x - __half2float(h0));
    __half l1 = __float2half_rn(v.y - __half2float(h1));
    size_t o = (size_t)r * (2 * K) + c;
    *(__half2*)(out + o)     = __halves2half2(h0, h1);
    *(__half2*)(out + o + K) = __halves2half2(l0, l1);
}

// W [K,N] fp32 -> out rows [row_off .. row_off+N), layout [N, 2K] : [hi | hi]
__global__ void split_w_kernel(const float* __restrict__ W, __half* __restrict__ out,
                               int K, int N, int row_off)
{
    __shared__ float t[32][33];
    int k0 = blockIdx.y * 32, n0 = blockIdx.x * 32;
    int tx = threadIdx.x, ty = threadIdx.y;   // 32 x 8
    #pragma unroll
    for (int i = 0; i < 32; i += 8)
        t[ty + i][tx] = W[(size_t)(k0 + ty + i) * N + n0 + tx];
    __syncthreads();
    #pragma unroll
    for (int i = 0; i < 32; i += 8) {
        int n = n0 + ty + i, k = k0 + tx;
        __half hi = __float2half_rn(t[tx][ty + i]);
        size_t o = (size_t)(n + row_off) * (2 * K) + k;
        out[o] = hi; out[o + K] = hi;
    }
}

// ======================= fp16 mma.sync GEMM ==================================
// C[M, *] = A'[M, KP2] @ B'[rows, KP2]^T. CTA tile 128x128, BK=32 elems.
// MODE 0: write fp32 C (Ntot stride). MODE 1: fused QKV epilogue (RoPE + fp16).
#define GSTRB 80
#define GSTAGE 20480
#define GNIT (KP2 / 32)                 // 128

template <int MODE>
__global__ __launch_bounds__(256) void gemm_h_kernel(
    const __half* __restrict__ A, const __half* __restrict__ B,
    float* __restrict__ C, int Ntot,
    const float* __restrict__ cs, const float* __restrict__ sn,
    __half* __restrict__ Qh, __half* __restrict__ Kh, __half* __restrict__ Vh)
{
    __shared__ __align__(16) char smbuf[2 * GSTAGE];
    const uint32_t smBase = smem_u32(smbuf);

    const int tid = threadIdx.x;
    const int lane = tid & 31;
    const int wid = tid >> 5;
    const int wm = wid >> 2, wn = wid & 3;
    const int m0 = blockIdx.y * 128;
    const int n0 = blockIdx.x * 128;

    const uint32_t offA = ((((lane >> 3) & 1) * 8 + (lane & 7)) * GSTRB) + ((lane >> 4) * 16);
    const uint32_t offB = (((lane >> 4) * 8 + (lane & 7)) * GSTRB) + (((lane >> 3) & 1) * 16);

    const char* Ab = (const char*)A;
    const char* Bb = (const char*)B;
    const int lrow = tid >> 2;
    const int lcol = tid & 3;

    auto load_stage = [&](int it_k, int s) {
        uint32_t base = smBase + s * GSTAGE;
        int kb = it_k * 64;
        #pragma unroll
        for (int half = 0; half < 2; half++) {
            int row = lrow + half * 64;
            cp16(base + row * GSTRB + lcol * 16,
                 Ab + (size_t)(m0 + row) * KPB2 + kb + lcol * 16);
        }
        #pragma unroll
        for (int half = 0; half < 2; half++) {
            int row = lrow + half * 64;
            cp16(base + 10240 + row * GSTRB + lcol * 16,
                 Bb + (size_t)(n0 + row) * KPB2 + kb + lcol * 16);
        }
        cp_commit();
    };

    float acc[4][4][4];
    #pragma unroll
    for (int i = 0; i < 4; i++)
        #pragma unroll
        for (int j = 0; j < 4; j++)
            #pragma unroll
            for (int k = 0; k < 4; k++) acc[i][j][k] = 0.f;

    load_stage(0, 0);

    for (int i = 0; i < GNIT; i++) {
        if (i + 1 < GNIT) { load_stage(i + 1, (i + 1) & 1); cp_wait<1>(); }
        else cp_wait<0>();
        __syncthreads();

        uint32_t sA = smBase + (i & 1) * GSTAGE;
        uint32_t sB = sA + 10240;
        #pragma unroll
        for (int ks = 0; ks < 2; ks++) {
            uint32_t afr[4][4], bfr[2][4];
            #pragma unroll
            for (int mt = 0; mt < 4; mt++)
                ldmx4(afr[mt], sA + (wm * 64 + mt * 16) * GSTRB + ks * 32 + offA);
            #pragma unroll
            for (int nt2 = 0; nt2 < 2; nt2++)
                ldmx4(bfr[nt2], sB + (wn * 32 + nt2 * 16) * GSTRB + ks * 32 + offB);
            #pragma unroll
            for (int mt = 0; mt < 4; mt++)
                #pragma unroll
                for (int nt = 0; nt < 4; nt++)
                    mma_f16(acc[mt][nt], afr[mt], bfr[nt >> 1][(nt & 1) * 2],
                            bfr[nt >> 1][(nt & 1) * 2 + 1]);
        }
        __syncthreads();
    }

    if (MODE == 0) {
        #pragma unroll
        for (int mt = 0; mt < 4; mt++) {
            int r0 = m0 + wm * 64 + mt * 16 + (lane >> 2);
            #pragma unroll
            for (int nt = 0; nt < 4; nt++) {
                int col = n0 + wn * 32 + nt * 8 + (lane & 3) * 2;
                *(float2*)(C + (size_t)r0 * Ntot + col) =
                    make_float2(acc[mt][nt][0], acc[mt][nt][1]);
                *(float2*)(C + (size_t)(r0 + 8) * Ntot + col) =
                    make_float2(acc[mt][nt][2], acc[mt][nt][3]);
            }
        }
    } else {
        // Fused QKV epilogue: n0 block entirely within one region
        // [0,2048)=Q (rope+scale), [2048,2560)=K (rope), [2560,3072)=V (cvt)
        #pragma unroll
        for (int mt = 0; mt < 4; mt++) {
            int r0 = m0 + wm * 64 + mt * 16 + (lane >> 2);
            int r1 = r0 + 8;
            int s0 = r0 & (SEQ - 1), s1 = r1 & (SEQ - 1);
            #pragma unroll
            for (int nt = 0; nt < 4; nt++) {
                int c = n0 + wn * 32 + nt * 8 + (lane & 3) * 2;
                float a0 = acc[mt][nt][0], a1 = acc[mt][nt][1];
                float a2 = acc[mt][nt][2], a3 = acc[mt][nt][3];
                if (n0 < DIM) {               // Q
                    int fi = (c & 127) >> 1;
                    float c0 = cs[s0 * 64 + fi], z0 = sn[s0 * 64 + fi];
                    float c1 = cs[s1 * 64 + fi], z1 = sn[s1 * 64 + fi];
                    *(__half2*)(Qh + (size_t)r0 * DIM + c) =
                        __floats2half2_rn((a0 * c0 - a1 * z0) * QMUL, (a0 * z0 + a1 * c0) * QMUL);
                    *(__half2*)(Qh + (size_t)r1 * DIM + c) =
                        __floats2half2_rn((a2 * c1 - a3 * z1) * QMUL, (a2 * z1 + a3 * c1) * QMUL);
                } else if (n0 < DIM + KVD) {  // K
                    int ck = c - DIM;
                    int fi = (ck & 127) >> 1;
                    float c0 = cs[s0 * 64 + fi], z0 = sn[s0 * 64 + fi];
                    float c1 = cs[s1 * 64 + fi], z1 = sn[s1 * 64 + fi];
                    *(__half2*)(Kh + (size_t)r0 * KVD + ck) =
                        __floats2half2_rn(a0 * c0 - a1 * z0, a0 * z0 + a1 * c0);
                    *(__half2*)(Kh + (size_t)r1 * KVD + ck) =
                        __floats2half2_rn(a2 * c1 - a3 * z1, a2 * z1 + a3 * c1);
                } else {                      // V
                    int cv = c - DIM - KVD;
                    *(__half2*)(Vh + (size_t)r0 * KVD + cv) = __floats2half2_rn(a0, a1);
                    *(__half2*)(Vh + (size_t)r1 * KVD + cv) = __floats2half2_rn(a2, a3);
                }
            }
        }
    }
}

// ---------------- Flash attention (fp16 mma.sync, double-buffered K/V) -------
// grid (SEQ/64, NH, BATCH), 128 threads. Epilogue writes hi/lo split into Ah.
#define FSTR 272
#define FTILE (64 * FSTR)               // 17408
#define FSMEM (5 * FTILE)               // 87040 : Q + 2*(K,V)

__global__ __launch_bounds__(128) void flash_mma_kernel(
    const __half* __restrict__ Q, const __half* __restrict__ K,
    const __half* __restrict__ V, __half* __restrict__ Ah)
{
    extern __shared__ char fsm[];
    const uint32_t smQ = smem_u32(fsm);

    const int tid = threadIdx.x;
    const int lane = tid & 31;
    const int wid = tid >> 5;
    const int qtile = blockIdx.x, h = blockIdx.y, b = blockIdx.z;
    const int g = h >> 2;
    const int m_base = qtile * 64;

    const uint32_t offQ = ((((lane >> 3) & 1) * 8 + (lane & 7)) * FSTR) + ((lane >> 4) * 16);
    const uint32_t offK = (((lane >> 4) * 8 + (lane & 7)) * FSTR) + (((lane >> 3) & 1) * 16);

    const char* Qb = (const char*)Q;
    const char* Kb = (const char*)K;
    const char* Vb = (const char*)V;

    auto load_kv = [&](int nt, int s) {
        uint32_t smK = smQ + FTILE + s * (2 * FTILE);
        uint32_t smV = smK + FTILE;
        #pragma unroll
        for (int it = 0; it < 16; it++) {
            int c = it * 128 + tid;
            int which = c >> 10;
            int row = (c >> 4) & 63, col = c & 15;
            uint32_t dst = (which ? smV : smK) + row * FSTR + col * 16;
            const char* srcb = which ? Vb : Kb;
            cp16(dst, srcb + ((size_t)(b * SEQ + nt * 64 + row) * KVD + g * HD) * 2 + col * 16);
        }
        cp_commit();
    };

    // Q tile (64 x 128 fp16)
    #pragma unroll
    for (int it = 0; it < 8; it++) {
        int c = it * 128 + tid;
        int row = c >> 4, col = c & 15;
        cp16(smQ + row * FSTR + col * 16,
             Qb + ((size_t)(b * SEQ + m_base + row) * DIM + h * HD) * 2 + col * 16);
    }
    cp_commit();
    load_kv(0, 0);
    cp_wait<1>();                         // Q done; kv0 may be in flight
    __syncthreads();

    uint32_t qfr[8][4];
    #pragma unroll
    for (int kd = 0; kd < 8; kd++)
        ldmx4(qfr[kd], smQ + (wid * 16) * FSTR + kd * 32 + offQ);

    float acc[16][4];
    #pragma unroll
    for (int i = 0; i < 16; i++)
        #pragma unroll
        for (int j = 0; j < 4; j++) acc[i][j] = 0.f;
    float mr0 = -1e30f, mr1 = -1e30f, l0 = 0.f, l1 = 0.f;

    for (int nt = 0; nt <= qtile; nt++) {
        if (nt < qtile) { load_kv(nt + 1, (nt + 1) & 1); cp_wait<1>(); }
        else cp_wait<0>();
        __syncthreads();

        uint32_t smK = smQ + FTILE + (nt & 1) * (2 * FTILE);
        uint32_t smV = smK + FTILE;

        // S = Q @ K^T (scale*log2e folded into Q)
        float s[8][4];
        #pragma unroll
        for (int i = 0; i < 8; i++)
            #pragma unroll
            for (int j = 0; j < 4; j++) s[i][j] = 0.f;
        #pragma unroll
        for (int kd = 0; kd < 8; kd++) {
            #pragma unroll
            for (int nt2 = 0; nt2 < 4; nt2++) {
                uint32_t bfr[4];
                ldmx4(bfr, smK + nt2 * 16 * FSTR + kd * 32 + offK);
                mma_f16(s[2 * nt2],     qfr[kd], bfr[0], bfr[1]);
                mma_f16(s[2 * nt2 + 1], qfr[kd], bfr[2], bfr[3]);
            }
        }

        if (nt == qtile) {                // diagonal tile mask
            int rl0 = wid * 16 + (lane >> 2);
            int rl1 = rl0 + 8;
            #pragma unroll
            for (int kt = 0; kt < 8; kt++) {
                int cl = kt * 8 + (lane & 3) * 2;
                if (cl     > rl0) s[kt][0] = -1e30f;
                if (cl + 1 > rl0) s[kt][1] = -1e30f;
                if (cl     > rl1) s[kt][2] = -1e30f;
                if (cl + 1 > rl1) s[kt][3] = -1e30f;
            }
        }

        float t0 = -1e30f, t1 = -1e30f;
        #pragma unroll
        for (int kt = 0; kt < 8; kt++) {
            t0 = fmaxf(t0, fmaxf(s[kt][0], s[kt][1]));
            t1 = fmaxf(t1, fmaxf(s[kt][2], s[kt][3]));
        }
        t0 = fmaxf(t0, __shfl_xor_sync(0xffffffffu, t0, 1));
        t0 = fmaxf(t0, __shfl_xor_sync(0xffffffffu, t0, 2));
        t1 = fmaxf(t1, __shfl_xor_sync(0xffffffffu, t1, 1));
        t1 = fmaxf(t1, __shfl_xor_sync(0xffffffffu, t1, 2));

        float mn0 = fmaxf(mr0, t0), mn1 = fmaxf(mr1, t1);
        float a0 = exp2f(mr0 - mn0), a1 = exp2f(mr1 - mn1);
        mr0 = mn0; mr1 = mn1;

        uint32_t pa[8][2];
        float lt0 = 0.f, lt1 = 0.f;
        #pragma unroll
        for (int kt = 0; kt < 8; kt++) {
            __half2 hp0 = h2exp2(__floats2half2_rn(s[kt][0] - mn0, s[kt][1] - mn0));
            __half2 hp1 = h2exp2(__floats2half2_rn(s[kt][2] - mn1, s[kt][3] - mn1));
            pa[kt][0] = h2_u32(hp0);
            pa[kt][1] = h2_u32(hp1);
            float2 f0 = __half22float2(hp0);
            float2 f1 = __half22float2(hp1);
            lt0 += f0.x + f0.y;
            lt1 += f1.x + f1.y;
        }
        lt0 += __shfl_xor_sync(0xffffffffu, lt0, 1);
        lt0 += __shfl_xor_sync(0xffffffffu, lt0, 2);
        lt1 += __shfl_xor_sync(0xffffffffu, lt1, 1);
        lt1 += __shfl_xor_sync(0xffffffffu, lt1, 2);
        l0 = l0 * a0 + lt0;
        l1 = l1 * a1 + lt1;

        #pragma unroll
        for (int i = 0; i < 16; i++) {
            acc[i][0] *= a0; acc[i][1] *= a0;
            acc[i][2] *= a1; acc[i][3] *= a1;
        }

        #pragma unroll
        for (int kt2 = 0; kt2 < 4; kt2++) {
            uint32_t pfr[4] = { pa[2 * kt2][0], pa[2 * kt2][1],
                                pa[2 * kt2 + 1][0], pa[2 * kt2 + 1][1] };
            #pragma unroll
            for (int dp = 0; dp < 8; dp++) {
                uint32_t vfr[4];
                ldmx4t(vfr, smV + kt2 * 16 * FSTR + dp * 32 + offQ);
                mma_f16(acc[2 * dp],     pfr, vfr[0], vfr[1]);
                mma_f16(acc[2 * dp + 1], pfr, vfr[2], vfr[3]);
            }
        }
        __syncthreads();
    }

    // epilogue: normalize + hi/lo fp16 split straight into Ah [token, 2*DIM]
    float inv0 = 1.f / l0, inv1 = 1.f / l1;
    int r0 = b * SEQ + m_base + wid * 16 + (lane >> 2);
    int r1 = r0 + 8;
    #pragma unroll
    for (int ntl = 0; ntl < 16; ntl++) {
        int c = h * HD + ntl * 8 + (lane & 3) * 2;
        float v0 = acc[ntl][0] * inv0, v1 = acc[ntl][1] * inv0;
        float v2 = acc[ntl][2] * inv1, v3 = acc[ntl][3] * inv1;
        __half h0 = __float2half_rn(v0), h1 = __float2half_rn(v1);
        __half h2 = __float2half_rn(v2), h3 = __float2half_rn(v3);
        *(__half2*)(Ah + (size_t)r0 * KP2 + c) = __halves2half2(h0, h1);
        *(__half2*)(Ah + (size_t)r0 * KP2 + DIM + c) =
            __halves2half2(__float2half_rn(v0 - __half2float(h0)),
                           __float2half_rn(v1 - __half2float(h1)));
        *(__half2*)(Ah + (size_t)r1 * KP2 + c) = __halves2half2(h2, h3);
        *(__half2*)(Ah + (size_t)r1 * KP2 + DIM + c) =
            __halves2half2(__float2half_rn(v2 - __half2float(h2)),
                           __float2half_rn(v3 - __half2float(h3)));
    }
}

// ---------------- launch -----------------------------------------------------
extern "C" void kernel_launch(void* const* d_in, const int* in_sizes, int n_in,
                              void* d_out, int out_size)
{
    const float* x  = (const float*)d_in[0];
    const float* fc = (const float*)d_in[1];
    const float* fs = (const float*)d_in[2];
    const float* Wq = (const float*)d_in[3];
    const float* Wk = (const float*)d_in[4];
    const float* Wv = (const float*)d_in[5];
    const float* Wo = (const float*)d_in[6];
    float* out = (float*)d_out;

    __half *Ah, *Wqkv, *Wo2, *Qh, *Kh, *Vh;
    cudaGetSymbolAddress((void**)&Ah,   g_Ah);
    cudaGetSymbolAddress((void**)&Wqkv, g_Wqkv);
    cudaGetSymbolAddress((void**)&Wo2,  g_Wo2);
    cudaGetSymbolAddress((void**)&Qh,   g_Qh);
    cudaGetSymbolAddress((void**)&Kh,   g_Kh);
    cudaGetSymbolAddress((void**)&Vh,   g_Vh);

    // splits
    {
        int n = MTOT * DIM / 2;
        split_x_kernel<<<(n + 255) / 256, 256>>>(x, Ah, MTOT, DIM);
        split_w_kernel<<<dim3(DIM / 32, DIM / 32), dim3(32, 8)>>>(Wq, Wqkv, DIM, DIM, 0);
        split_w_kernel<<<dim3(KVD / 32, DIM / 32), dim3(32, 8)>>>(Wk, Wqkv, DIM, KVD, DIM);
        split_w_kernel<<<dim3(KVD / 32, DIM / 32), dim3(32, 8)>>>(Wv, Wqkv, DIM, KVD, DIM + KVD);
        split_w_kernel<<<dim3(DIM / 32, DIM / 32), dim3(32, 8)>>>(Wo, Wo2, DIM, DIM, 0);
    }

    // fused QKV projection + RoPE + fp16 convert
    gemm_h_kernel<1><<<dim3(NQKV / 128, MTOT / 128), 256>>>(
        Ah, Wqkv, nullptr, 0, fc, fs, Qh, Kh, Vh);

    // flash attention (fp16 tensor cores, double-buffered) -> Ah split
    cudaFuncSetAttribute(flash_mma_kernel, cudaFuncAttributeMaxDynamicSharedMemorySize, FSMEM);
    flash_mma_kernel<<<dim3(SEQ / 64, NH, BATCH), 128, FSMEM>>>(Qh, Kh, Vh, Ah);

    // output projection
    gemm_h_kernel<0><<<dim3(DIM / 128, MTOT / 128), 256>>>(
        Ah, Wo2, out, DIM, nullptr, nullptr, nullptr, nullptr, nullptr);
}

// round 5
// speedup vs baseline: 9.0842x; 1.0004x over previous
#include <cuda_runtime.h>
#include <cuda_bf16.h>
#include <cuda_fp16.h>
#include <math.h>
#include <stdint.h>

#define BATCH 2
#define SEQ 2048
#define DIM 2048
#define NH 16
#define NKV 4
#define HD 128
#define MTOT (BATCH * SEQ)          // 4096
#define KVD (NKV * HD)              // 512
#define NQKV (DIM + 2 * KVD)        // 3072
#define KP2 (2 * DIM)               // 4096: A stored [hi | lo]
#define KPB2 (KP2 * 2)              // A row bytes
#define WRB (DIM * 2)               // weight row bytes (K=2048 fp16)

// ---------------- scratch (static device globals) ----------------------------
__device__ __half g_Ah  [(size_t)MTOT * KP2];   // activations split [hi|lo]
__device__ __half g_Wqkv[(size_t)NQKV * DIM];   // [WqT;WkT;WvT] hi only [N,K]
__device__ __half g_Wo2 [(size_t)DIM  * DIM];   // WoT hi only
__device__ __half g_Qh  [(size_t)MTOT * DIM];
__device__ __half g_Kh  [(size_t)MTOT * KVD];
__device__ __half g_Vh  [(size_t)MTOT * KVD];

#define QMUL (0.08838834764831845f * 1.4426950408889634f)   // scale * log2(e)

// ======================= small PTX helpers ===================================
__device__ __forceinline__ uint32_t smem_u32(const void* p) {
    uint32_t a;
    asm("{ .reg .u64 t; cvta.to.shared.u64 t, %1; cvt.u32.u64 %0, t; }" : "=r"(a) : "l"(p));
    return a;
}
__device__ __forceinline__ void cp16(uint32_t dst, const void* src) {
    asm volatile("cp.async.cg.shared.global [%0], [%1], 16;" :: "r"(dst), "l"(src));
}
__device__ __forceinline__ void cp_commit() { asm volatile("cp.async.commit_group;"); }
template <int N> __device__ __forceinline__ void cp_wait() {
    asm volatile("cp.async.wait_group %0;" :: "n"(N));
}
__device__ __forceinline__ void ldmx4(uint32_t* r, uint32_t a) {
    asm volatile("ldmatrix.sync.aligned.m8n8.x4.shared.b16 {%0,%1,%2,%3}, [%4];"
                 : "=r"(r[0]), "=r"(r[1]), "=r"(r[2]), "=r"(r[3]) : "r"(a));
}
__device__ __forceinline__ void ldmx4t(uint32_t* r, uint32_t a) {
    asm volatile("ldmatrix.sync.aligned.m8n8.x4.trans.shared.b16 {%0,%1,%2,%3}, [%4];"
                 : "=r"(r[0]), "=r"(r[1]), "=r"(r[2]), "=r"(r[3]) : "r"(a));
}
__device__ __forceinline__ void mma_f16(float* c, const uint32_t* a, uint32_t b0, uint32_t b1) {
    asm volatile("mma.sync.aligned.m16n8k16.row.col.f32.f16.f16.f32 "
                 "{%0,%1,%2,%3},{%4,%5,%6,%7},{%8,%9},{%0,%1,%2,%3};"
                 : "+f"(c[0]), "+f"(c[1]), "+f"(c[2]), "+f"(c[3])
                 : "r"(a[0]), "r"(a[1]), "r"(a[2]), "r"(a[3]), "r"(b0), "r"(b1));
}
// fp16-accumulator MMA (2x rate) for the lo correction term
__device__ __forceinline__ void mma_f16h(uint32_t* c, const uint32_t* a, uint32_t b0, uint32_t b1) {
    asm volatile("mma.sync.aligned.m16n8k16.row.col.f16.f16.f16.f16 "
                 "{%0,%1},{%2,%3,%4,%5},{%6,%7},{%0,%1};"
                 : "+r"(c[0]), "+r"(c[1])
                 : "r"(a[0]), "r"(a[1]), "r"(a[2]), "r"(a[3]), "r"(b0), "r"(b1));
}
__device__ __forceinline__ uint32_t h2_u32(__half2 h) {
    return *reinterpret_cast<uint32_t*>(&h);
}

// ======================= split conversions ===================================
// x [M,K] fp32 -> out [M, 2K] fp16 : [hi | lo]
__global__ void split_x_kernel(const float* __restrict__ A, __half* __restrict__ out,
                               int M, int K)
{
    int i = blockIdx.x * blockDim.x + threadIdx.x;
    int tot = M * (K / 2);
    if (i >= tot) return;
    int r = i / (K / 2), c = (i % (K / 2)) * 2;
    float2 v = *(const float2*)(A + (size_t)r * K + c);
    __half h0 = __float2half_rn(v.x), h1 = __float2half_rn(v.y);
    __half l0 = __float2half_rn(v.x - __half2float(h0));
    __half l1 = __float2half_rn(v.y - __half2float(h1));
    size_t o = (size_t)r * (2 * K) + c;
    *(__half2*)(out + o)     = __halves2half2(h0, h1);
    *(__half2*)(out + o + K) = __halves2half2(l0, l1);
}

// W [K,N] fp32 -> out rows [row_off..row_off+N), layout [*, K] fp16 hi
__global__ void split_w_kernel(const float* __restrict__ W, __half* __restrict__ out,
                               int K, int N, int row_off)
{
    __shared__ float t[32][33];
    int k0 = blockIdx.y * 32, n0 = blockIdx.x * 32;
    int tx = threadIdx.x, ty = threadIdx.y;   // 32 x 8
    #pragma unroll
    for (int i = 0; i < 32; i += 8)
        t[ty + i][tx] = W[(size_t)(k0 + ty + i) * N + n0 + tx];
    __syncthreads();
    #pragma unroll
    for (int i = 0; i < 32; i += 8) {
        int n = n0 + ty + i, k = k0 + tx;
        out[(size_t)(n + row_off) * K + k] = __float2half_rn(t[tx][ty + i]);
    }
}

// ======================= fp16 mma.sync GEMM (shared-B, hi/lo) ================
// C[M,*] = (Ahi + Alo)[M,K] @ B[N,K]^T. CTA 128x128, BK=32, 64 k-iters,
// 4-stage cp.async pipeline. lo-term uses fp16 accumulators (2x HMMA rate).
#define GSTRB 80                    // 64B data + 16B pad per row
#define GSUB  10240                 // 128 rows * 80B per sub-tile
#define GSTG  (3 * GSUB)            // Ahi + Alo + B per stage = 30720
#define GNST  4
#define GSMEM (GNST * GSTG)         // 122880
#define GNIT  (DIM / 32)            // 64

template <int MODE>
__global__ __launch_bounds__(256) void gemm_h_kernel(
    const __half* __restrict__ A, const __half* __restrict__ B,
    float* __restrict__ C, int Ntot,
    const float* __restrict__ cs, const float* __restrict__ sn,
    __half* __restrict__ Qh, __half* __restrict__ Kh, __half* __restrict__ Vh)
{
    extern __shared__ __align__(16) char smbuf[];
    const uint32_t smBase = smem_u32(smbuf);

    const int tid = threadIdx.x;
    const int lane = tid & 31;
    const int wid = tid >> 5;
    const int wm = wid >> 2, wn = wid & 3;
    const int m0 = blockIdx.y * 128;
    const int n0 = blockIdx.x * 128;

    const uint32_t offA = ((((lane >> 3) & 1) * 8 + (lane & 7)) * GSTRB) + ((lane >> 4) * 16);
    const uint32_t offB = (((lane >> 4) * 8 + (lane & 7)) * GSTRB) + (((lane >> 3) & 1) * 16);

    const char* Ab = (const char*)A;
    const char* Bb = (const char*)B;

    auto load_stage = [&](int kc, int slot) {
        uint32_t base = smBase + slot * GSTG;
        int kb = kc * 64;                       // byte offset within K
        #pragma unroll
        for (int j = 0; j < 2; j++) {
            int c = tid + j * 256;
            int row = c >> 2, col = (c & 3) * 16;
            const char* arow = Ab + (size_t)(m0 + row) * KPB2 + kb + col;
            cp16(base + row * GSTRB + col, arow);                    // A hi
            cp16(base + GSUB + row * GSTRB + col, arow + DIM * 2);   // A lo
            cp16(base + 2 * GSUB + row * GSTRB + col,
                 Bb + (size_t)(n0 + row) * WRB + kb + col);          // B
        }
        cp_commit();
    };

    float acc[4][4][4];
    uint32_t accl[4][4][2];
    #pragma unroll
    for (int i = 0; i < 4; i++)
        #pragma unroll
        for (int j = 0; j < 4; j++) {
            #pragma unroll
            for (int k = 0; k < 4; k++) acc[i][j][k] = 0.f;
            accl[i][j][0] = 0u; accl[i][j][1] = 0u;
        }

    load_stage(0, 0);
    load_stage(1, 1);
    load_stage(2, 2);

    for (int i = 0; i < GNIT; i++) {
        if (i < GNIT - 2) cp_wait<2>();
        else if (i == GNIT - 2) cp_wait<1>();
        else cp_wait<0>();
        __syncthreads();
        if (i + 3 < GNIT) load_stage(i + 3, (i + 3) & 3);

        uint32_t sA  = smBase + (i & 3) * GSTG;
        uint32_t sAl = sA + GSUB;
        uint32_t sB  = sA + 2 * GSUB;
        #pragma unroll
        for (int ks = 0; ks < 2; ks++) {
            uint32_t bfr[2][4];
            #pragma unroll
            for (int nt2 = 0; nt2 < 2; nt2++)
                ldmx4(bfr[nt2], sB + (wn * 32 + nt2 * 16) * GSTRB + ks * 32 + offB);
            uint32_t afr[4][4];
            #pragma unroll
            for (int mt = 0; mt < 4; mt++)
                ldmx4(afr[mt], sA + (wm * 64 + mt * 16) * GSTRB + ks * 32 + offA);
            #pragma unroll
            for (int mt = 0; mt < 4; mt++)
                #pragma unroll
                for (int nt = 0; nt < 4; nt++)
                    mma_f16(acc[mt][nt], afr[mt], bfr[nt >> 1][(nt & 1) * 2],
                            bfr[nt >> 1][(nt & 1) * 2 + 1]);
            #pragma unroll
            for (int mt = 0; mt < 4; mt++)
                ldmx4(afr[mt], sAl + (wm * 64 + mt * 16) * GSTRB + ks * 32 + offA);
            #pragma unroll
            for (int mt = 0; mt < 4; mt++)
                #pragma unroll
                for (int nt = 0; nt < 4; nt++)
                    mma_f16h(accl[mt][nt], afr[mt], bfr[nt >> 1][(nt & 1) * 2],
                             bfr[nt >> 1][(nt & 1) * 2 + 1]);
        }
    }

    #pragma unroll
    for (int mt = 0; mt < 4; mt++) {
        int r0 = m0 + wm * 64 + mt * 16 + (lane >> 2);
        int r1 = r0 + 8;
        int s0 = r0 & (SEQ - 1), s1 = r1 & (SEQ - 1);
        #pragma unroll
        for (int nt = 0; nt < 4; nt++) {
            float2 lo01 = __half22float2(*(__half2*)&accl[mt][nt][0]);
            float2 lo23 = __half22float2(*(__half2*)&accl[mt][nt][1]);
            float a0 = acc[mt][nt][0] + lo01.x, a1 = acc[mt][nt][1] + lo01.y;
            float a2 = acc[mt][nt][2] + lo23.x, a3 = acc[mt][nt][3] + lo23.y;
            int c = n0 + wn * 32 + nt * 8 + (lane & 3) * 2;
            if (MODE == 0) {
                *(float2*)(C + (size_t)r0 * Ntot + c) = make_float2(a0, a1);
                *(float2*)(C + (size_t)r1 * Ntot + c) = make_float2(a2, a3);
            } else {
                if (n0 < DIM) {               // Q: rope + scale
                    int fi = (c & 127) >> 1;
                    float c0 = cs[s0 * 64 + fi], z0 = sn[s0 * 64 + fi];
                    float c1 = cs[s1 * 64 + fi], z1 = sn[s1 * 64 + fi];
                    *(__half2*)(Qh + (size_t)r0 * DIM + c) =
                        __floats2half2_rn((a0 * c0 - a1 * z0) * QMUL, (a0 * z0 + a1 * c0) * QMUL);
                    *(__half2*)(Qh + (size_t)r1 * DIM + c) =
                        __floats2half2_rn((a2 * c1 - a3 * z1) * QMUL, (a2 * z1 + a3 * c1) * QMUL);
                } else if (n0 < DIM + KVD) {  // K: rope
                    int ck = c - DIM;
                    int fi = (ck & 127) >> 1;
                    float c0 = cs[s0 * 64 + fi], z0 = sn[s0 * 64 + fi];
                    float c1 = cs[s1 * 64 + fi], z1 = sn[s1 * 64 + fi];
                    *(__half2*)(Kh + (size_t)r0 * KVD + ck) =
                        __floats2half2_rn(a0 * c0 - a1 * z0, a0 * z0 + a1 * c0);
                    *(__half2*)(Kh + (size_t)r1 * KVD + ck) =
                        __floats2half2_rn(a2 * c1 - a3 * z1, a2 * z1 + a3 * c1);
                } else {                      // V: cvt
                    int cv = c - DIM - KVD;
                    *(__half2*)(Vh + (size_t)r0 * KVD + cv) = __floats2half2_rn(a0, a1);
                    *(__half2*)(Vh + (size_t)r1 * KVD + cv) = __floats2half2_rn(a2, a3);
                }
            }
        }
    }
}

// ---------------- Flash attention (fp16 mma.sync, double-buffered K/V) -------
#define FSTR 272
#define FTILE (64 * FSTR)               // 17408
#define FSMEM (5 * FTILE)               // 87040

__global__ __launch_bounds__(128) void flash_mma_kernel(
    const __half* __restrict__ Q, const __half* __restrict__ K,
    const __half* __restrict__ V, __half* __restrict__ Ah)
{
    extern __shared__ char fsm[];
    const uint32_t smQ = smem_u32(fsm);

    const int tid = threadIdx.x;
    const int lane = tid & 31;
    const int wid = tid >> 5;
    const int qtile = gridDim.x - 1 - blockIdx.x;   // heavy tiles first
    const int h = blockIdx.y, b = blockIdx.z;
    const int g = h >> 2;
    const int m_base = qtile * 64;

    const uint32_t offQ = ((((lane >> 3) & 1) * 8 + (lane & 7)) * FSTR) + ((lane >> 4) * 16);
    const uint32_t offK = (((lane >> 4) * 8 + (lane & 7)) * FSTR) + (((lane >> 3) & 1) * 16);

    const char* Qb = (const char*)Q;
    const char* Kb = (const char*)K;
    const char* Vb = (const char*)V;

    auto load_kv = [&](int nt, int s) {
        uint32_t smK = smQ + FTILE + s * (2 * FTILE);
        uint32_t smV = smK + FTILE;
        #pragma unroll
        for (int it = 0; it < 16; it++) {
            int c = it * 128 + tid;
            int which = c >> 10;
            int row = (c >> 4) & 63, col = c & 15;
            uint32_t dst = (which ? smV : smK) + row * FSTR + col * 16;
            const char* srcb = which ? Vb : Kb;
            cp16(dst, srcb + ((size_t)(b * SEQ + nt * 64 + row) * KVD + g * HD) * 2 + col * 16);
        }
        cp_commit();
    };

    #pragma unroll
    for (int it = 0; it < 8; it++) {
        int c = it * 128 + tid;
        int row = c >> 4, col = c & 15;
        cp16(smQ + row * FSTR + col * 16,
             Qb + ((size_t)(b * SEQ + m_base + row) * DIM + h * HD) * 2 + col * 16);
    }
    cp_commit();
    load_kv(0, 0);
    cp_wait<1>();
    __syncthreads();

    uint32_t qfr[8][4];
    #pragma unroll
    for (int kd = 0; kd < 8; kd++)
        ldmx4(qfr[kd], smQ + (wid * 16) * FSTR + kd * 32 + offQ);

    float acc[16][4];
    #pragma unroll
    for (int i = 0; i < 16; i++)
        #pragma unroll
        for (int j = 0; j < 4; j++) acc[i][j] = 0.f;
    float mr0 = -1e30f, mr1 = -1e30f, l0 = 0.f, l1 = 0.f;

    for (int nt = 0; nt <= qtile; nt++) {
        if (nt < qtile) { load_kv(nt + 1, (nt + 1) & 1); cp_wait<1>(); }
        else cp_wait<0>();
        __syncthreads();

        uint32_t smK = smQ + FTILE + (nt & 1) * (2 * FTILE);
        uint32_t smV = smK + FTILE;

        float s[8][4];
        #pragma unroll
        for (int i = 0; i < 8; i++)
            #pragma unroll
            for (int j = 0; j < 4; j++) s[i][j] = 0.f;
        #pragma unroll
        for (int kd = 0; kd < 8; kd++) {
            #pragma unroll
            for (int nt2 = 0; nt2 < 4; nt2++) {
                uint32_t bfr[4];
                ldmx4(bfr, smK + nt2 * 16 * FSTR + kd * 32 + offK);
                mma_f16(s[2 * nt2],     qfr[kd], bfr[0], bfr[1]);
                mma_f16(s[2 * nt2 + 1], qfr[kd], bfr[2], bfr[3]);
            }
        }

        if (nt == qtile) {
            int rl0 = wid * 16 + (lane >> 2);
            int rl1 = rl0 + 8;
            #pragma unroll
            for (int kt = 0; kt < 8; kt++) {
                int cl = kt * 8 + (lane & 3) * 2;
                if (cl     > rl0) s[kt][0] = -1e30f;
                if (cl + 1 > rl0) s[kt][1] = -1e30f;
                if (cl     > rl1) s[kt][2] = -1e30f;
                if (cl + 1 > rl1) s[kt][3] = -1e30f;
            }
        }

        float t0 = -1e30f, t1 = -1e30f;
        #pragma unroll
        for (int kt = 0; kt < 8; kt++) {
            t0 = fmaxf(t0, fmaxf(s[kt][0], s[kt][1]));
            t1 = fmaxf(t1, fmaxf(s[kt][2], s[kt][3]));
        }
        t0 = fmaxf(t0, __shfl_xor_sync(0xffffffffu, t0, 1));
        t0 = fmaxf(t0, __shfl_xor_sync(0xffffffffu, t0, 2));
        t1 = fmaxf(t1, __shfl_xor_sync(0xffffffffu, t1, 1));
        t1 = fmaxf(t1, __shfl_xor_sync(0xffffffffu, t1, 2));

        float mn0 = fmaxf(mr0, t0), mn1 = fmaxf(mr1, t1);
        float a0 = exp2f(mr0 - mn0), a1 = exp2f(mr1 - mn1);
        mr0 = mn0; mr1 = mn1;

        uint32_t pa[8][2];
        float lt0 = 0.f, lt1 = 0.f;
        #pragma unroll
        for (int kt = 0; kt < 8; kt++) {
            __half2 hp0 = h2exp2(__floats2half2_rn(s[kt][0] - mn0, s[kt][1] - mn0));
            __half2 hp1 = h2exp2(__floats2half2_rn(s[kt][2] - mn1, s[kt][3] - mn1));
            pa[kt][0] = h2_u32(hp0);
            pa[kt][1] = h2_u32(hp1);
            float2 f0 = __half22float2(hp0);
            float2 f1 = __half22float2(hp1);
            lt0 += f0.x + f0.y;
            lt1 += f1.x + f1.y;
        }
        lt0 += __shfl_xor_sync(0xffffffffu, lt0, 1);
        lt0 += __shfl_xor_sync(0xffffffffu, lt0, 2);
        lt1 += __shfl_xor_sync(0xffffffffu, lt1, 1);
        lt1 += __shfl_xor_sync(0xffffffffu, lt1, 2);
        l0 = l0 * a0 + lt0;
        l1 = l1 * a1 + lt1;

        #pragma unroll
        for (int i = 0; i < 16; i++) {
            acc[i][0] *= a0; acc[i][1] *= a0;
            acc[i][2] *= a1; acc[i][3] *= a1;
        }

        #pragma unroll
        for (int kt2 = 0; kt2 < 4; kt2++) {
            uint32_t pfr[4] = { pa[2 * kt2][0], pa[2 * kt2][1],
                                pa[2 * kt2 + 1][0], pa[2 * kt2 + 1][1] };
            #pragma unroll
            for (int dp = 0; dp < 8; dp++) {
                uint32_t vfr[4];
                ldmx4t(vfr, smV + kt2 * 16 * FSTR + dp * 32 + offQ);
                mma_f16(acc[2 * dp],     pfr, vfr[0], vfr[1]);
                mma_f16(acc[2 * dp + 1], pfr, vfr[2], vfr[3]);
            }
        }
        __syncthreads();
    }

    // epilogue: normalize + hi/lo fp16 split into Ah [token, 2*DIM]
    float inv0 = 1.f / l0, inv1 = 1.f / l1;
    int r0 = b * SEQ + m_base + wid * 16 + (lane >> 2);
    int r1 = r0 + 8;
    #pragma unroll
    for (int ntl = 0; ntl < 16; ntl++) {
        int c = h * HD + ntl * 8 + (lane & 3) * 2;
        float v0 = acc[ntl][0] * inv0, v1 = acc[ntl][1] * inv0;
        float v2 = acc[ntl][2] * inv1, v3 = acc[ntl][3] * inv1;
        __half h0 = __float2half_rn(v0), h1 = __float2half_rn(v1);
        __half h2 = __float2half_rn(v2), h3 = __float2half_rn(v3);
        *(__half2*)(Ah + (size_t)r0 * KP2 + c) = __halves2half2(h0, h1);
        *(__half2*)(Ah + (size_t)r0 * KP2 + DIM + c) =
            __halves2half2(__float2half_rn(v0 - __half2float(h0)),
                           __float2half_rn(v1 - __half2float(h1)));
        *(__half2*)(Ah + (size_t)r1 * KP2 + c) = __halves2half2(h2, h3);
        *(__half2*)(Ah + (size_t)r1 * KP2 + DIM + c) =
            __halves2half2(__float2half_rn(v2 - __half2float(h2)),
                           __float2half_rn(v3 - __half2float(h3)));
    }
}

// ---------------- launch -----------------------------------------------------
extern "C" void kernel_launch(void* const* d_in, const int* in_sizes, int n_in,
                              void* d_out, int out_size)
{
    const float* x  = (const float*)d_in[0];
    const float* fc = (const float*)d_in[1];
    const float* fs = (const float*)d_in[2];
    const float* Wq = (const float*)d_in[3];
    const float* Wk = (const float*)d_in[4];
    const float* Wv = (const float*)d_in[5];
    const float* Wo = (const float*)d_in[6];
    float* out = (float*)d_out;

    __half *Ah, *Wqkv, *Wo2, *Qh, *Kh, *Vh;
    cudaGetSymbolAddress((void**)&Ah,   g_Ah);
    cudaGetSymbolAddress((void**)&Wqkv, g_Wqkv);
    cudaGetSymbolAddress((void**)&Wo2,  g_Wo2);
    cudaGetSymbolAddress((void**)&Qh,   g_Qh);
    cudaGetSymbolAddress((void**)&Kh,   g_Kh);
    cudaGetSymbolAddress((void**)&Vh,   g_Vh);

    cudaFuncSetAttribute(gemm_h_kernel<0>, cudaFuncAttributeMaxDynamicSharedMemorySize, GSMEM);
    cudaFuncSetAttribute(gemm_h_kernel<1>, cudaFuncAttributeMaxDynamicSharedMemorySize, GSMEM);
    cudaFuncSetAttribute(flash_mma_kernel, cudaFuncAttributeMaxDynamicSharedMemorySize, FSMEM);

    // splits
    {
        int n = MTOT * DIM / 2;
        split_x_kernel<<<(n + 255) / 256, 256>>>(x, Ah, MTOT, DIM);
        split_w_kernel<<<dim3(DIM / 32, DIM / 32), dim3(32, 8)>>>(Wq, Wqkv, DIM, DIM, 0);
        split_w_kernel<<<dim3(KVD / 32, DIM / 32), dim3(32, 8)>>>(Wk, Wqkv, DIM, KVD, DIM);
        split_w_kernel<<<dim3(KVD / 32, DIM / 32), dim3(32, 8)>>>(Wv, Wqkv, DIM, KVD, DIM + KVD);
        split_w_kernel<<<dim3(DIM / 32, DIM / 32), dim3(32, 8)>>>(Wo, Wo2, DIM, DIM, 0);
    }

    // fused QKV projection + RoPE + fp16 convert
    gemm_h_kernel<1><<<dim3(NQKV / 128, MTOT / 128), 256, GSMEM>>>(
        Ah, Wqkv, nullptr, 0, fc, fs, Qh, Kh, Vh);

    // flash attention -> Ah split
    flash_mma_kernel<<<dim3(SEQ / 64, NH, BATCH), 128, FSMEM>>>(Qh, Kh, Vh, Ah);

    // output projection
    gemm_h_kernel<0><<<dim3(DIM / 128, MTOT / 128), 256, GSMEM>>>(
        Ah, Wo2, out, DIM, nullptr, nullptr, nullptr, nullptr, nullptr);
}

// round 6
// speedup vs baseline: 11.6232x; 1.2795x over previous
#include <cuda_runtime.h>
#include <cuda_bf16.h>
#include <cuda_fp16.h>
#include <math.h>
#include <stdint.h>

#define BATCH 2
#define SEQ 2048
#define DIM 2048
#define NH 16
#define NKV 4
#define HD 128
#define MTOT (BATCH * SEQ)          // 4096
#define KVD (NKV * HD)              // 512
#define NQKV (DIM + 2 * KVD)        // 3072
#define KP2 (2 * DIM)               // 4096: activations stored [hi | lo]
#define KPB2 (KP2 * 2)              // activation row bytes
#define WRB (DIM * 2)               // weight row bytes (K=2048 fp16)

// ---------------- scratch (static device globals) ----------------------------
__device__ __half g_Ah  [(size_t)MTOT * KP2];   // activations split [hi|lo]
__device__ __half g_Wqkv[(size_t)NQKV * DIM];   // [WqT;WkT;WvT] fp16 [N,K]
__device__ __half g_Wo2 [(size_t)DIM  * DIM];   // WoT fp16
__device__ __half g_Qh  [(size_t)MTOT * DIM];
__device__ __half g_Kh  [(size_t)MTOT * KVD];
__device__ __half g_Vh  [(size_t)MTOT * KVD];

#define QMUL (0.08838834764831845f * 1.4426950408889634f)   // scale * log2(e)

// ======================= small PTX helpers ===================================
__device__ __forceinline__ uint32_t smem_u32(const void* p) {
    uint32_t a;
    asm("{ .reg .u64 t; cvta.to.shared.u64 t, %1; cvt.u32.u64 %0, t; }" : "=r"(a) : "l"(p));
    return a;
}
__device__ __forceinline__ void cp16(uint32_t dst, const void* src) {
    asm volatile("cp.async.cg.shared.global [%0], [%1], 16;" :: "r"(dst), "l"(src));
}
__device__ __forceinline__ void cp_commit() { asm volatile("cp.async.commit_group;"); }
template <int N> __device__ __forceinline__ void cp_wait() {
    asm volatile("cp.async.wait_group %0;" :: "n"(N));
}
__device__ __forceinline__ void ldmx4(uint32_t* r, uint32_t a) {
    asm volatile("ldmatrix.sync.aligned.m8n8.x4.shared.b16 {%0,%1,%2,%3}, [%4];"
                 : "=r"(r[0]), "=r"(r[1]), "=r"(r[2]), "=r"(r[3]) : "r"(a));
}
__device__ __forceinline__ void ldmx4t(uint32_t* r, uint32_t a) {
    asm volatile("ldmatrix.sync.aligned.m8n8.x4.trans.shared.b16 {%0,%1,%2,%3}, [%4];"
                 : "=r"(r[0]), "=r"(r[1]), "=r"(r[2]), "=r"(r[3]) : "r"(a));
}
__device__ __forceinline__ void mma_f16(float* c, const uint32_t* a, uint32_t b0, uint32_t b1) {
    asm volatile("mma.sync.aligned.m16n8k16.row.col.f32.f16.f16.f32 "
                 "{%0,%1,%2,%3},{%4,%5,%6,%7},{%8,%9},{%0,%1,%2,%3};"
                 : "+f"(c[0]), "+f"(c[1]), "+f"(c[2]), "+f"(c[3])
                 : "r"(a[0]), "r"(a[1]), "r"(a[2]), "r"(a[3]), "r"(b0), "r"(b1));
}
__device__ __forceinline__ void mma_f16h(uint32_t* c, const uint32_t* a, uint32_t b0, uint32_t b1) {
    asm volatile("mma.sync.aligned.m16n8k16.row.col.f16.f16.f16.f16 "
                 "{%0,%1},{%2,%3,%4,%5},{%6,%7},{%0,%1};"
                 : "+r"(c[0]), "+r"(c[1])
                 : "r"(a[0]), "r"(a[1]), "r"(a[2]), "r"(a[3]), "r"(b0), "r"(b1));
}
__device__ __forceinline__ uint32_t h2_u32(__half2 h) {
    return *reinterpret_cast<uint32_t*>(&h);
}

// ======================= split conversions ===================================
// x [M,K] fp32 -> out [M, 2K] fp16 : [hi | lo]
__global__ void split_x_kernel(const float* __restrict__ A, __half* __restrict__ out,
                               int M, int K)
{
    int i = blockIdx.x * blockDim.x + threadIdx.x;
    int tot = M * (K / 2);
    if (i >= tot) return;
    int r = i / (K / 2), c = (i % (K / 2)) * 2;
    float2 v = *(const float2*)(A + (size_t)r * K + c);
    __half h0 = __float2half_rn(v.x), h1 = __float2half_rn(v.y);
    __half l0 = __float2half_rn(v.x - __half2float(h0));
    __half l1 = __float2half_rn(v.y - __half2float(h1));
    size_t o = (size_t)r * (2 * K) + c;
    *(__half2*)(out + o)     = __halves2half2(h0, h1);
    *(__half2*)(out + o + K) = __halves2half2(l0, l1);
}

// W [K,N] fp32 -> out rows [row_off..row_off+N), layout [*, K] fp16
__global__ void split_w_kernel(const float* __restrict__ W, __half* __restrict__ out,
                               int K, int N, int row_off)
{
    __shared__ float t[32][33];
    int k0 = blockIdx.y * 32, n0 = blockIdx.x * 32;
    int tx = threadIdx.x, ty = threadIdx.y;   // 32 x 8
    #pragma unroll
    for (int i = 0; i < 32; i += 8)
        t[ty + i][tx] = W[(size_t)(k0 + ty + i) * N + n0 + tx];
    __syncthreads();
    #pragma unroll
    for (int i = 0; i < 32; i += 8) {
        int n = n0 + ty + i, k = k0 + tx;
        out[(size_t)(n + row_off) * K + k] = __float2half_rn(t[tx][ty + i]);
    }
}

// ======================= fp16 mma.sync GEMM ==================================
// C = A @ B^T over K=2048, CTA 128x128, BK=32, 4-stage cp.async.
// LO=1: adds lo-A correction pass (fp16 accumulators). MODE 1: fused QKV epi.
#define GSTRB 80                    // 64B data + 16B pad per row
#define GSUB  10240                 // 128 rows * 80B per sub-tile
#define GNIT  (DIM / 32)            // 64

template <int MODE, int LO>
__global__ __launch_bounds__(256) void gemm_h_kernel(
    const __half* __restrict__ A, const __half* __restrict__ B,
    float* __restrict__ C, int Ntot,
    const float* __restrict__ cs, const float* __restrict__ sn,
    __half* __restrict__ Qh, __half* __restrict__ Kh, __half* __restrict__ Vh)
{
    constexpr int STG = (LO ? 3 : 2) * GSUB;     // bytes per stage
    extern __shared__ __align__(16) char smbuf[];
    const uint32_t smBase = smem_u32(smbuf);

    const int tid = threadIdx.x;
    const int lane = tid & 31;
    const int wid = tid >> 5;
    const int wm = wid >> 2, wn = wid & 3;
    const int m0 = blockIdx.y * 128;
    const int n0 = blockIdx.x * 128;

    const uint32_t offA = ((((lane >> 3) & 1) * 8 + (lane & 7)) * GSTRB) + ((lane >> 4) * 16);
    const uint32_t offB = (((lane >> 4) * 8 + (lane & 7)) * GSTRB) + (((lane >> 3) & 1) * 16);

    const char* Ab = (const char*)A;
    const char* Bb = (const char*)B;

    auto load_stage = [&](int kc, int slot) {
        uint32_t base = smBase + slot * STG;
        int kb = kc * 64;
        #pragma unroll
        for (int j = 0; j < 2; j++) {
            int c = tid + j * 256;
            int row = c >> 2, col = (c & 3) * 16;
            const char* arow = Ab + (size_t)(m0 + row) * KPB2 + kb + col;
            cp16(base + row * GSTRB + col, arow);                        // A hi
            if (LO)
                cp16(base + GSUB + row * GSTRB + col, arow + DIM * 2);   // A lo
            cp16(base + (LO ? 2 : 1) * GSUB + row * GSTRB + col,
                 Bb + (size_t)(n0 + row) * WRB + kb + col);              // B
        }
        cp_commit();
    };

    float acc[4][4][4];
    uint32_t accl[4][4][2];
    #pragma unroll
    for (int i = 0; i < 4; i++)
        #pragma unroll
        for (int j = 0; j < 4; j++) {
            #pragma unroll
            for (int k = 0; k < 4; k++) acc[i][j][k] = 0.f;
            accl[i][j][0] = 0u; accl[i][j][1] = 0u;
        }

    load_stage(0, 0);
    load_stage(1, 1);
    load_stage(2, 2);

    for (int i = 0; i < GNIT; i++) {
        if (i < GNIT - 2) cp_wait<2>();
        else if (i == GNIT - 2) cp_wait<1>();
        else cp_wait<0>();
        __syncthreads();
        if (i + 3 < GNIT) load_stage(i + 3, (i + 3) & 3);

        uint32_t sA  = smBase + (i & 3) * STG;
        uint32_t sAl = sA + GSUB;
        uint32_t sB  = sA + (LO ? 2 : 1) * GSUB;
        #pragma unroll
        for (int ks = 0; ks < 2; ks++) {
            uint32_t bfr[2][4];
            #pragma unroll
            for (int nt2 = 0; nt2 < 2; nt2++)
                ldmx4(bfr[nt2], sB + (wn * 32 + nt2 * 16) * GSTRB + ks * 32 + offB);
            uint32_t afr[4][4];
            #pragma unroll
            for (int mt = 0; mt < 4; mt++)
                ldmx4(afr[mt], sA + (wm * 64 + mt * 16) * GSTRB + ks * 32 + offA);
            #pragma unroll
            for (int mt = 0; mt < 4; mt++)
                #pragma unroll
                for (int nt = 0; nt < 4; nt++)
                    mma_f16(acc[mt][nt], afr[mt], bfr[nt >> 1][(nt & 1) * 2],
                            bfr[nt >> 1][(nt & 1) * 2 + 1]);
            if (LO) {
                #pragma unroll
                for (int mt = 0; mt < 4; mt++)
                    ldmx4(afr[mt], sAl + (wm * 64 + mt * 16) * GSTRB + ks * 32 + offA);
                #pragma unroll
                for (int mt = 0; mt < 4; mt++)
                    #pragma unroll
                    for (int nt = 0; nt < 4; nt++)
                        mma_f16h(accl[mt][nt], afr[mt], bfr[nt >> 1][(nt & 1) * 2],
                                 bfr[nt >> 1][(nt & 1) * 2 + 1]);
            }
        }
    }

    #pragma unroll
    for (int mt = 0; mt < 4; mt++) {
        int r0 = m0 + wm * 64 + mt * 16 + (lane >> 2);
        int r1 = r0 + 8;
        int s0 = r0 & (SEQ - 1), s1 = r1 & (SEQ - 1);
        #pragma unroll
        for (int nt = 0; nt < 4; nt++) {
            float a0 = acc[mt][nt][0], a1 = acc[mt][nt][1];
            float a2 = acc[mt][nt][2], a3 = acc[mt][nt][3];
            if (LO) {
                float2 lo01 = __half22float2(*(__half2*)&accl[mt][nt][0]);
                float2 lo23 = __half22float2(*(__half2*)&accl[mt][nt][1]);
                a0 += lo01.x; a1 += lo01.y; a2 += lo23.x; a3 += lo23.y;
            }
            int c = n0 + wn * 32 + nt * 8 + (lane & 3) * 2;
            if (MODE == 0) {
                *(float2*)(C + (size_t)r0 * Ntot + c) = make_float2(a0, a1);
                *(float2*)(C + (size_t)r1 * Ntot + c) = make_float2(a2, a3);
            } else {
                if (n0 < DIM) {               // Q: rope + scale
                    int fi = (c & 127) >> 1;
                    float c0 = cs[s0 * 64 + fi], z0 = sn[s0 * 64 + fi];
                    float c1 = cs[s1 * 64 + fi], z1 = sn[s1 * 64 + fi];
                    *(__half2*)(Qh + (size_t)r0 * DIM + c) =
                        __floats2half2_rn((a0 * c0 - a1 * z0) * QMUL, (a0 * z0 + a1 * c0) * QMUL);
                    *(__half2*)(Qh + (size_t)r1 * DIM + c) =
                        __floats2half2_rn((a2 * c1 - a3 * z1) * QMUL, (a2 * z1 + a3 * c1) * QMUL);
                } else if (n0 < DIM + KVD) {  // K: rope
                    int ck = c - DIM;
                    int fi = (ck & 127) >> 1;
                    float c0 = cs[s0 * 64 + fi], z0 = sn[s0 * 64 + fi];
                    float c1 = cs[s1 * 64 + fi], z1 = sn[s1 * 64 + fi];
                    *(__half2*)(Kh + (size_t)r0 * KVD + ck) =
                        __floats2half2_rn(a0 * c0 - a1 * z0, a0 * z0 + a1 * c0);
                    *(__half2*)(Kh + (size_t)r1 * KVD + ck) =
                        __floats2half2_rn(a2 * c1 - a3 * z1, a2 * z1 + a3 * c1);
                } else {                      // V: cvt
                    int cv = c - DIM - KVD;
                    *(__half2*)(Vh + (size_t)r0 * KVD + cv) = __floats2half2_rn(a0, a1);
                    *(__half2*)(Vh + (size_t)r1 * KVD + cv) = __floats2half2_rn(a2, a3);
                }
            }
        }
    }
}

// ---------------- Flash attention (fp16 mma.sync, double-buffered K/V) -------
#define FSTR 272
#define FTILE (64 * FSTR)               // 17408
#define FSMEM (5 * FTILE)               // 87040

__global__ __launch_bounds__(128) void flash_mma_kernel(
    const __half* __restrict__ Q, const __half* __restrict__ K,
    const __half* __restrict__ V, __half* __restrict__ Ah)
{
    extern __shared__ char fsm[];
    const uint32_t smQ = smem_u32(fsm);

    const int tid = threadIdx.x;
    const int lane = tid & 31;
    const int wid = tid >> 5;
    const int qtile = gridDim.x - 1 - blockIdx.x;   // heavy tiles first
    const int h = blockIdx.y, b = blockIdx.z;
    const int g = h >> 2;
    const int m_base = qtile * 64;

    const uint32_t offQ = ((((lane >> 3) & 1) * 8 + (lane & 7)) * FSTR) + ((lane >> 4) * 16);
    const uint32_t offK = (((lane >> 4) * 8 + (lane & 7)) * FSTR) + (((lane >> 3) & 1) * 16);

    const char* Qb = (const char*)Q;
    const char* Kb = (const char*)K;
    const char* Vb = (const char*)V;

    auto load_kv = [&](int nt, int s) {
        uint32_t smK = smQ + FTILE + s * (2 * FTILE);
        uint32_t smV = smK + FTILE;
        #pragma unroll
        for (int it = 0; it < 16; it++) {
            int c = it * 128 + tid;
            int which = c >> 10;
            int row = (c >> 4) & 63, col = c & 15;
            uint32_t dst = (which ? smV : smK) + row * FSTR + col * 16;
            const char* srcb = which ? Vb : Kb;
            cp16(dst, srcb + ((size_t)(b * SEQ + nt * 64 + row) * KVD + g * HD) * 2 + col * 16);
        }
        cp_commit();
    };

    #pragma unroll
    for (int it = 0; it < 8; it++) {
        int c = it * 128 + tid;
        int row = c >> 4, col = c & 15;
        cp16(smQ + row * FSTR + col * 16,
             Qb + ((size_t)(b * SEQ + m_base + row) * DIM + h * HD) * 2 + col * 16);
    }
    cp_commit();
    load_kv(0, 0);
    cp_wait<1>();
    __syncthreads();

    uint32_t qfr[8][4];
    #pragma unroll
    for (int kd = 0; kd < 8; kd++)
        ldmx4(qfr[kd], smQ + (wid * 16) * FSTR + kd * 32 + offQ);

    float acc[16][4];
    #pragma unroll
    for (int i = 0; i < 16; i++)
        #pragma unroll
        for (int j = 0; j < 4; j++) acc[i][j] = 0.f;
    float mr0 = -1e30f, mr1 = -1e30f, l0 = 0.f, l1 = 0.f;

    for (int nt = 0; nt <= qtile; nt++) {
        if (nt < qtile) { load_kv(nt + 1, (nt + 1) & 1); cp_wait<1>(); }
        else cp_wait<0>();
        __syncthreads();

        uint32_t smK = smQ + FTILE + (nt & 1) * (2 * FTILE);
        uint32_t smV = smK + FTILE;

        float s[8][4];
        #pragma unroll
        for (int i = 0; i < 8; i++)
            #pragma unroll
            for (int j = 0; j < 4; j++) s[i][j] = 0.f;
        #pragma unroll
        for (int kd = 0; kd < 8; kd++) {
            #pragma unroll
            for (int nt2 = 0; nt2 < 4; nt2++) {
                uint32_t bfr[4];
                ldmx4(bfr, smK + nt2 * 16 * FSTR + kd * 32 + offK);
                mma_f16(s[2 * nt2],     qfr[kd], bfr[0], bfr[1]);
                mma_f16(s[2 * nt2 + 1], qfr[kd], bfr[2], bfr[3]);
            }
        }

        if (nt == qtile) {
            int rl0 = wid * 16 + (lane >> 2);
            int rl1 = rl0 + 8;
            #pragma unroll
            for (int kt = 0; kt < 8; kt++) {
                int cl = kt * 8 + (lane & 3) * 2;
                if (cl     > rl0) s[kt][0] = -1e30f;
                if (cl + 1 > rl0) s[kt][1] = -1e30f;
                if (cl     > rl1) s[kt][2] = -1e30f;
                if (cl + 1 > rl1) s[kt][3] = -1e30f;
            }
        }

        float t0 = -1e30f, t1 = -1e30f;
        #pragma unroll
        for (int kt = 0; kt < 8; kt++) {
            t0 = fmaxf(t0, fmaxf(s[kt][0], s[kt][1]));
            t1 = fmaxf(t1, fmaxf(s[kt][2], s[kt][3]));
        }
        t0 = fmaxf(t0, __shfl_xor_sync(0xffffffffu, t0, 1));
        t0 = fmaxf(t0, __shfl_xor_sync(0xffffffffu, t0, 2));
        t1 = fmaxf(t1, __shfl_xor_sync(0xffffffffu, t1, 1));
        t1 = fmaxf(t1, __shfl_xor_sync(0xffffffffu, t1, 2));

        float mn0 = fmaxf(mr0, t0), mn1 = fmaxf(mr1, t1);
        float a0 = exp2f(mr0 - mn0), a1 = exp2f(mr1 - mn1);
        mr0 = mn0; mr1 = mn1;

        uint32_t pa[8][2];
        float lt0 = 0.f, lt1 = 0.f;
        #pragma unroll
        for (int kt = 0; kt < 8; kt++) {
            __half2 hp0 = h2exp2(__floats2half2_rn(s[kt][0] - mn0, s[kt][1] - mn0));
            __half2 hp1 = h2exp2(__floats2half2_rn(s[kt][2] - mn1, s[kt][3] - mn1));
            pa[kt][0] = h2_u32(hp0);
            pa[kt][1] = h2_u32(hp1);
            float2 f0 = __half22float2(hp0);
            float2 f1 = __half22float2(hp1);
            lt0 += f0.x + f0.y;
            lt1 += f1.x + f1.y;
        }
        lt0 += __shfl_xor_sync(0xffffffffu, lt0, 1);
        lt0 += __shfl_xor_sync(0xffffffffu, lt0, 2);
        lt1 += __shfl_xor_sync(0xffffffffu, lt1, 1);
        lt1 += __shfl_xor_sync(0xffffffffu, lt1, 2);
        l0 = l0 * a0 + lt0;
        l1 = l1 * a1 + lt1;

        #pragma unroll
        for (int i = 0; i < 16; i++) {
            acc[i][0] *= a0; acc[i][1] *= a0;
            acc[i][2] *= a1; acc[i][3] *= a1;
        }

        #pragma unroll
        for (int kt2 = 0; kt2 < 4; kt2++) {
            uint32_t pfr[4] = { pa[2 * kt2][0], pa[2 * kt2][1],
                                pa[2 * kt2 + 1][0], pa[2 * kt2 + 1][1] };
            #pragma unroll
            for (int dp = 0; dp < 8; dp++) {
                uint32_t vfr[4];
                ldmx4t(vfr, smV + kt2 * 16 * FSTR + dp * 32 + offQ);
                mma_f16(acc[2 * dp],     pfr, vfr[0], vfr[1]);
                mma_f16(acc[2 * dp + 1], pfr, vfr[2], vfr[3]);
            }
        }
        __syncthreads();
    }

    // epilogue: normalize + hi/lo fp16 split into Ah [token, 2*DIM]
    float inv0 = 1.f / l0, inv1 = 1.f / l1;
    int r0 = b * SEQ + m_base + wid * 16 + (lane >> 2);
    int r1 = r0 + 8;
    #pragma unroll
    for (int ntl = 0; ntl < 16; ntl++) {
        int c = h * HD + ntl * 8 + (lane & 3) * 2;
        float v0 = acc[ntl][0] * inv0, v1 = acc[ntl][1] * inv0;
        float v2 = acc[ntl][2] * inv1, v3 = acc[ntl][3] * inv1;
        __half h0 = __float2half_rn(v0), h1 = __float2half_rn(v1);
        __half h2 = __float2half_rn(v2), h3 = __float2half_rn(v3);
        *(__half2*)(Ah + (size_t)r0 * KP2 + c) = __halves2half2(h0, h1);
        *(__half2*)(Ah + (size_t)r0 * KP2 + DIM + c) =
            __halves2half2(__float2half_rn(v0 - __half2float(h0)),
                           __float2half_rn(v1 - __half2float(h1)));
        *(__half2*)(Ah + (size_t)r1 * KP2 + c) = __halves2half2(h2, h3);
        *(__half2*)(Ah + (size_t)r1 * KP2 + DIM + c) =
            __halves2half2(__float2half_rn(v2 - __half2float(h2)),
                           __float2half_rn(v3 - __half2float(h3)));
    }
}

// ---------------- launch -----------------------------------------------------
extern "C" void kernel_launch(void* const* d_in, const int* in_sizes, int n_in,
                              void* d_out, int out_size)
{
    const float* x  = (const float*)d_in[0];
    const float* fc = (const float*)d_in[1];
    const float* fs = (const float*)d_in[2];
    const float* Wq = (const float*)d_in[3];
    const float* Wk = (const float*)d_in[4];
    const float* Wv = (const float*)d_in[5];
    const float* Wo = (const float*)d_in[6];
    float* out = (float*)d_out;

    __half *Ah, *Wqkv, *Wo2, *Qh, *Kh, *Vh;
    cudaGetSymbolAddress((void**)&Ah,   g_Ah);
    cudaGetSymbolAddress((void**)&Wqkv, g_Wqkv);
    cudaGetSymbolAddress((void**)&Wo2,  g_Wo2);
    cudaGetSymbolAddress((void**)&Qh,   g_Qh);
    cudaGetSymbolAddress((void**)&Kh,   g_Kh);
    cudaGetSymbolAddress((void**)&Vh,   g_Vh);

    const int SM_QKV = 4 * 2 * GSUB;     // 81920
    const int SM_WO  = 4 * 3 * GSUB;     // 122880
    cudaFuncSetAttribute((const void*)gemm_h_kernel<1, 0>,
                         cudaFuncAttributeMaxDynamicSharedMemorySize, SM_QKV);
    cudaFuncSetAttribute((const void*)gemm_h_kernel<0, 1>,
                         cudaFuncAttributeMaxDynamicSharedMemorySize, SM_WO);
    cudaFuncSetAttribute(flash_mma_kernel, cudaFuncAttributeMaxDynamicSharedMemorySize, FSMEM);

    // splits
    {
        int n = MTOT * DIM / 2;
        split_x_kernel<<<(n + 255) / 256, 256>>>(x, Ah, MTOT, DIM);
        split_w_kernel<<<dim3(DIM / 32, DIM / 32), dim3(32, 8)>>>(Wq, Wqkv, DIM, DIM, 0);
        split_w_kernel<<<dim3(KVD / 32, DIM / 32), dim3(32, 8)>>>(Wk, Wqkv, DIM, KVD, DIM);
        split_w_kernel<<<dim3(KVD / 32, DIM / 32), dim3(32, 8)>>>(Wv, Wqkv, DIM, KVD, DIM + KVD);
        split_w_kernel<<<dim3(DIM / 32, DIM / 32), dim3(32, 8)>>>(Wo, Wo2, DIM, DIM, 0);
    }

    // fused QKV projection (hi only) + RoPE + fp16 convert
    gemm_h_kernel<1, 0><<<dim3(NQKV / 128, MTOT / 128), 256, SM_QKV>>>(
        Ah, Wqkv, nullptr, 0, fc, fs, Qh, Kh, Vh);

    // flash attention -> Ah split
    flash_mma_kernel<<<dim3(SEQ / 64, NH, BATCH), 128, FSMEM>>>(Qh, Kh, Vh, Ah);

    // output projection (hi + lo, full precision path)
    gemm_h_kernel<0, 1><<<dim3(DIM / 128, MTOT / 128), 256, SM_WO>>>(
        Ah, Wo2, out, DIM, nullptr, nullptr, nullptr, nullptr, nullptr);
}

// round 7
// speedup vs baseline: 14.8801x; 1.2802x over previous
#include <cuda_runtime.h>
#include <cuda_bf16.h>
#include <cuda_fp16.h>
#include <math.h>
#include <stdint.h>

#define BATCH 2
#define SEQ 2048
#define DIM 2048
#define NH 16
#define NKV 4
#define HD 128
#define MTOT (BATCH * SEQ)          // 4096
#define KVD (NKV * HD)              // 512
#define NQKV (DIM + 2 * KVD)        // 3072
#define WRB (DIM * 2)               // row bytes for fp16 [*, K=2048]

// ---------------- scratch (static device globals) ----------------------------
__device__ __half g_Ah  [(size_t)MTOT * DIM];   // activations fp16 (x, then attn out)
__device__ __half g_Wqkv[(size_t)NQKV * DIM];   // [WqT;WkT;WvT] fp16 [N,K]
__device__ __half g_Wo2 [(size_t)DIM  * DIM];   // WoT fp16
__device__ __half g_Qh  [(size_t)MTOT * DIM];
__device__ __half g_Kh  [(size_t)MTOT * KVD];
__device__ __half g_Vh  [(size_t)MTOT * KVD];

#define QMUL (0.08838834764831845f * 1.4426950408889634f)   // scale * log2(e)

// ======================= small PTX helpers ===================================
__device__ __forceinline__ uint32_t smem_u32(const void* p) {
    uint32_t a;
    asm("{ .reg .u64 t; cvta.to.shared.u64 t, %1; cvt.u32.u64 %0, t; }" : "=r"(a) : "l"(p));
    return a;
}
__device__ __forceinline__ void cp16(uint32_t dst, const void* src) {
    asm volatile("cp.async.cg.shared.global [%0], [%1], 16;" :: "r"(dst), "l"(src));
}
__device__ __forceinline__ void cp_commit() { asm volatile("cp.async.commit_group;"); }
template <int N> __device__ __forceinline__ void cp_wait() {
    asm volatile("cp.async.wait_group %0;" :: "n"(N));
}
__device__ __forceinline__ void ldmx4(uint32_t* r, uint32_t a) {
    asm volatile("ldmatrix.sync.aligned.m8n8.x4.shared.b16 {%0,%1,%2,%3}, [%4];"
                 : "=r"(r[0]), "=r"(r[1]), "=r"(r[2]), "=r"(r[3]) : "r"(a));
}
__device__ __forceinline__ void ldmx4t(uint32_t* r, uint32_t a) {
    asm volatile("ldmatrix.sync.aligned.m8n8.x4.trans.shared.b16 {%0,%1,%2,%3}, [%4];"
                 : "=r"(r[0]), "=r"(r[1]), "=r"(r[2]), "=r"(r[3]) : "r"(a));
}
__device__ __forceinline__ void mma_f16(float* c, const uint32_t* a, uint32_t b0, uint32_t b1) {
    asm volatile("mma.sync.aligned.m16n8k16.row.col.f32.f16.f16.f32 "
                 "{%0,%1,%2,%3},{%4,%5,%6,%7},{%8,%9},{%0,%1,%2,%3};"
                 : "+f"(c[0]), "+f"(c[1]), "+f"(c[2]), "+f"(c[3])
                 : "r"(a[0]), "r"(a[1]), "r"(a[2]), "r"(a[3]), "r"(b0), "r"(b1));
}
__device__ __forceinline__ uint32_t h2_u32(__half2 h) {
    return *reinterpret_cast<uint32_t*>(&h);
}

// ======================= conversions =========================================
// x [M,K] fp32 -> fp16
__global__ void cvt_x_kernel(const float* __restrict__ A, __half* __restrict__ out, int n2)
{
    int i = blockIdx.x * blockDim.x + threadIdx.x;
    if (i >= n2) return;
    float4 v = *(const float4*)(A + 4 * (size_t)i);
    __half2 a = __floats2half2_rn(v.x, v.y);
    __half2 b = __floats2half2_rn(v.z, v.w);
    *(uint2*)(out + 4 * (size_t)i) = make_uint2(h2_u32(a), h2_u32(b));
}

// W [K,N] fp32 -> out rows [row_off..row_off+N), layout [*, K] fp16
__global__ void split_w_kernel(const float* __restrict__ W, __half* __restrict__ out,
                               int K, int N, int row_off)
{
    __shared__ float t[32][33];
    int k0 = blockIdx.y * 32, n0 = blockIdx.x * 32;
    int tx = threadIdx.x, ty = threadIdx.y;   // 32 x 8
    #pragma unroll
    for (int i = 0; i < 32; i += 8)
        t[ty + i][tx] = W[(size_t)(k0 + ty + i) * N + n0 + tx];
    __syncthreads();
    #pragma unroll
    for (int i = 0; i < 32; i += 8) {
        int n = n0 + ty + i, k = k0 + tx;
        out[(size_t)(n + row_off) * K + k] = __float2half_rn(t[tx][ty + i]);
    }
}

// ======================= fp16 mma.sync GEMM ==================================
// C = A[M,K] @ B[N,K]^T, K=2048. CTA 128x128, BK=32, 4-stage cp.async.
// MODE 0: fp32 C out. MODE 1: fused QKV epilogue (RoPE + fp16 Q/K/V).
#define GSTRB 80                    // 64B data + 16B pad per row
#define GSUB  10240                 // 128 rows * 80B per sub-tile
#define GSTG  (2 * GSUB)            // A + B per stage
#define GSMEM (4 * GSTG)            // 81920
#define GNIT  (DIM / 32)            // 64

template <int MODE>
__global__ __launch_bounds__(256) void gemm_h_kernel(
    const __half* __restrict__ A, const __half* __restrict__ B,
    float* __restrict__ C, int Ntot,
    const float* __restrict__ cs, const float* __restrict__ sn,
    __half* __restrict__ Qh, __half* __restrict__ Kh, __half* __restrict__ Vh)
{
    extern __shared__ __align__(16) char smbuf[];
    const uint32_t smBase = smem_u32(smbuf);

    const int tid = threadIdx.x;
    const int lane = tid & 31;
    const int wid = tid >> 5;
    const int wm = wid >> 2, wn = wid & 3;
    const int m0 = blockIdx.y * 128;
    const int n0 = blockIdx.x * 128;

    const uint32_t offA = ((((lane >> 3) & 1) * 8 + (lane & 7)) * GSTRB) + ((lane >> 4) * 16);
    const uint32_t offB = (((lane >> 4) * 8 + (lane & 7)) * GSTRB) + (((lane >> 3) & 1) * 16);

    const char* Ab = (const char*)A;
    const char* Bb = (const char*)B;

    auto load_stage = [&](int kc, int slot) {
        uint32_t base = smBase + slot * GSTG;
        int kb = kc * 64;
        #pragma unroll
        for (int j = 0; j < 2; j++) {
            int c = tid + j * 256;
            int row = c >> 2, col = (c & 3) * 16;
            cp16(base + row * GSTRB + col,
                 Ab + (size_t)(m0 + row) * WRB + kb + col);              // A
            cp16(base + GSUB + row * GSTRB + col,
                 Bb + (size_t)(n0 + row) * WRB + kb + col);              // B
        }
        cp_commit();
    };

    float acc[4][4][4];
    #pragma unroll
    for (int i = 0; i < 4; i++)
        #pragma unroll
        for (int j = 0; j < 4; j++)
            #pragma unroll
            for (int k = 0; k < 4; k++) acc[i][j][k] = 0.f;

    load_stage(0, 0);
    load_stage(1, 1);
    load_stage(2, 2);

    for (int i = 0; i < GNIT; i++) {
        if (i < GNIT - 2) cp_wait<2>();
        else if (i == GNIT - 2) cp_wait<1>();
        else cp_wait<0>();
        __syncthreads();
        if (i + 3 < GNIT) load_stage(i + 3, (i + 3) & 3);

        uint32_t sA = smBase + (i & 3) * GSTG;
        uint32_t sB = sA + GSUB;
        #pragma unroll
        for (int ks = 0; ks < 2; ks++) {
            uint32_t bfr[2][4];
            #pragma unroll
            for (int nt2 = 0; nt2 < 2; nt2++)
                ldmx4(bfr[nt2], sB + (wn * 32 + nt2 * 16) * GSTRB + ks * 32 + offB);
            uint32_t afr[4][4];
            #pragma unroll
            for (int mt = 0; mt < 4; mt++)
                ldmx4(afr[mt], sA + (wm * 64 + mt * 16) * GSTRB + ks * 32 + offA);
            #pragma unroll
            for (int mt = 0; mt < 4; mt++)
                #pragma unroll
                for (int nt = 0; nt < 4; nt++)
                    mma_f16(acc[mt][nt], afr[mt], bfr[nt >> 1][(nt & 1) * 2],
                            bfr[nt >> 1][(nt & 1) * 2 + 1]);
        }
    }

    #pragma unroll
    for (int mt = 0; mt < 4; mt++) {
        int r0 = m0 + wm * 64 + mt * 16 + (lane >> 2);
        int r1 = r0 + 8;
        int s0 = r0 & (SEQ - 1), s1 = r1 & (SEQ - 1);
        #pragma unroll
        for (int nt = 0; nt < 4; nt++) {
            float a0 = acc[mt][nt][0], a1 = acc[mt][nt][1];
            float a2 = acc[mt][nt][2], a3 = acc[mt][nt][3];
            int c = n0 + wn * 32 + nt * 8 + (lane & 3) * 2;
            if (MODE == 0) {
                *(float2*)(C + (size_t)r0 * Ntot + c) = make_float2(a0, a1);
                *(float2*)(C + (size_t)r1 * Ntot + c) = make_float2(a2, a3);
            } else {
                if (n0 < DIM) {               // Q: rope + scale
                    int fi = (c & 127) >> 1;
                    float c0 = cs[s0 * 64 + fi], z0 = sn[s0 * 64 + fi];
                    float c1 = cs[s1 * 64 + fi], z1 = sn[s1 * 64 + fi];
                    *(__half2*)(Qh + (size_t)r0 * DIM + c) =
                        __floats2half2_rn((a0 * c0 - a1 * z0) * QMUL, (a0 * z0 + a1 * c0) * QMUL);
                    *(__half2*)(Qh + (size_t)r1 * DIM + c) =
                        __floats2half2_rn((a2 * c1 - a3 * z1) * QMUL, (a2 * z1 + a3 * c1) * QMUL);
                } else if (n0 < DIM + KVD) {  // K: rope
                    int ck = c - DIM;
                    int fi = (ck & 127) >> 1;
                    float c0 = cs[s0 * 64 + fi], z0 = sn[s0 * 64 + fi];
                    float c1 = cs[s1 * 64 + fi], z1 = sn[s1 * 64 + fi];
                    *(__half2*)(Kh + (size_t)r0 * KVD + ck) =
                        __floats2half2_rn(a0 * c0 - a1 * z0, a0 * z0 + a1 * c0);
                    *(__half2*)(Kh + (size_t)r1 * KVD + ck) =
                        __floats2half2_rn(a2 * c1 - a3 * z1, a2 * z1 + a3 * c1);
                } else {                      // V: cvt
                    int cv = c - DIM - KVD;
                    *(__half2*)(Vh + (size_t)r0 * KVD + cv) = __floats2half2_rn(a0, a1);
                    *(__half2*)(Vh + (size_t)r1 * KVD + cv) = __floats2half2_rn(a2, a3);
                }
            }
        }
    }
}

// ---------------- Flash attention (fp16 mma.sync, double-buffered K/V) -------
#define FSTR 272
#define FTILE (64 * FSTR)               // 17408
#define FSMEM (5 * FTILE)               // 87040

__global__ __launch_bounds__(128) void flash_mma_kernel(
    const __half* __restrict__ Q, const __half* __restrict__ K,
    const __half* __restrict__ V, __half* __restrict__ Ah)
{
    extern __shared__ char fsm[];
    const uint32_t smQ = smem_u32(fsm);

    const int tid = threadIdx.x;
    const int lane = tid & 31;
    const int wid = tid >> 5;
    const int qtile = gridDim.x - 1 - blockIdx.x;   // heavy tiles first
    const int h = blockIdx.y, b = blockIdx.z;
    const int g = h >> 2;
    const int m_base = qtile * 64;

    const uint32_t offQ = ((((lane >> 3) & 1) * 8 + (lane & 7)) * FSTR) + ((lane >> 4) * 16);
    const uint32_t offK = (((lane >> 4) * 8 + (lane & 7)) * FSTR) + (((lane >> 3) & 1) * 16);

    const char* Qb = (const char*)Q;
    const char* Kb = (const char*)K;
    const char* Vb = (const char*)V;

    auto load_kv = [&](int nt, int s) {
        uint32_t smK = smQ + FTILE + s * (2 * FTILE);
        uint32_t smV = smK + FTILE;
        #pragma unroll
        for (int it = 0; it < 16; it++) {
            int c = it * 128 + tid;
            int which = c >> 10;
            int row = (c >> 4) & 63, col = c & 15;
            uint32_t dst = (which ? smV : smK) + row * FSTR + col * 16;
            const char* srcb = which ? Vb : Kb;
            cp16(dst, srcb + ((size_t)(b * SEQ + nt * 64 + row) * KVD + g * HD) * 2 + col * 16);
        }
        cp_commit();
    };

    #pragma unroll
    for (int it = 0; it < 8; it++) {
        int c = it * 128 + tid;
        int row = c >> 4, col = c & 15;
        cp16(smQ + row * FSTR + col * 16,
             Qb + ((size_t)(b * SEQ + m_base + row) * DIM + h * HD) * 2 + col * 16);
    }
    cp_commit();
    load_kv(0, 0);
    cp_wait<1>();
    __syncthreads();

    uint32_t qfr[8][4];
    #pragma unroll
    for (int kd = 0; kd < 8; kd++)
        ldmx4(qfr[kd], smQ + (wid * 16) * FSTR + kd * 32 + offQ);

    float acc[16][4];
    #pragma unroll
    for (int i = 0; i < 16; i++)
        #pragma unroll
        for (int j = 0; j < 4; j++) acc[i][j] = 0.f;
    float mr0 = -1e30f, mr1 = -1e30f, l0 = 0.f, l1 = 0.f;

    for (int nt = 0; nt <= qtile; nt++) {
        if (nt < qtile) { load_kv(nt + 1, (nt + 1) & 1); cp_wait<1>(); }
        else cp_wait<0>();
        __syncthreads();

        uint32_t smK = smQ + FTILE + (nt & 1) * (2 * FTILE);
        uint32_t smV = smK + FTILE;

        float s[8][4];
        #pragma unroll
        for (int i = 0; i < 8; i++)
            #pragma unroll
            for (int j = 0; j < 4; j++) s[i][j] = 0.f;
        #pragma unroll
        for (int kd = 0; kd < 8; kd++) {
            #pragma unroll
            for (int nt2 = 0; nt2 < 4; nt2++) {
                uint32_t bfr[4];
                ldmx4(bfr, smK + nt2 * 16 * FSTR + kd * 32 + offK);
                mma_f16(s[2 * nt2],     qfr[kd], bfr[0], bfr[1]);
                mma_f16(s[2 * nt2 + 1], qfr[kd], bfr[2], bfr[3]);
            }
        }

        if (nt == qtile) {
            int rl0 = wid * 16 + (lane >> 2);
            int rl1 = rl0 + 8;
            #pragma unroll
            for (int kt = 0; kt < 8; kt++) {
                int cl = kt * 8 + (lane & 3) * 2;
                if (cl     > rl0) s[kt][0] = -1e30f;
                if (cl + 1 > rl0) s[kt][1] = -1e30f;
                if (cl     > rl1) s[kt][2] = -1e30f;
                if (cl + 1 > rl1) s[kt][3] = -1e30f;
            }
        }

        float t0 = -1e30f, t1 = -1e30f;
        #pragma unroll
        for (int kt = 0; kt < 8; kt++) {
            t0 = fmaxf(t0, fmaxf(s[kt][0], s[kt][1]));
            t1 = fmaxf(t1, fmaxf(s[kt][2], s[kt][3]));
        }
        t0 = fmaxf(t0, __shfl_xor_sync(0xffffffffu, t0, 1));
        t0 = fmaxf(t0, __shfl_xor_sync(0xffffffffu, t0, 2));
        t1 = fmaxf(t1, __shfl_xor_sync(0xffffffffu, t1, 1));
        t1 = fmaxf(t1, __shfl_xor_sync(0xffffffffu, t1, 2));

        float mn0 = fmaxf(mr0, t0), mn1 = fmaxf(mr1, t1);
        float a0 = exp2f(mr0 - mn0), a1 = exp2f(mr1 - mn1);
        mr0 = mn0; mr1 = mn1;

        uint32_t pa[8][2];
        float lt0 = 0.f, lt1 = 0.f;
        #pragma unroll
        for (int kt = 0; kt < 8; kt++) {
            __half2 hp0 = h2exp2(__floats2half2_rn(s[kt][0] - mn0, s[kt][1] - mn0));
            __half2 hp1 = h2exp2(__floats2half2_rn(s[kt][2] - mn1, s[kt][3] - mn1));
            pa[kt][0] = h2_u32(hp0);
            pa[kt][1] = h2_u32(hp1);
            float2 f0 = __half22float2(hp0);
            float2 f1 = __half22float2(hp1);
            lt0 += f0.x + f0.y;
            lt1 += f1.x + f1.y;
        }
        lt0 += __shfl_xor_sync(0xffffffffu, lt0, 1);
        lt0 += __shfl_xor_sync(0xffffffffu, lt0, 2);
        lt1 += __shfl_xor_sync(0xffffffffu, lt1, 1);
        lt1 += __shfl_xor_sync(0xffffffffu, lt1, 2);
        l0 = l0 * a0 + lt0;
        l1 = l1 * a1 + lt1;

        #pragma unroll
        for (int i = 0; i < 16; i++) {
            acc[i][0] *= a0; acc[i][1] *= a0;
            acc[i][2] *= a1; acc[i][3] *= a1;
        }

        #pragma unroll
        for (int kt2 = 0; kt2 < 4; kt2++) {
            uint32_t pfr[4] = { pa[2 * kt2][0], pa[2 * kt2][1],
                                pa[2 * kt2 + 1][0], pa[2 * kt2 + 1][1] };
            #pragma unroll
            for (int dp = 0; dp < 8; dp++) {
                uint32_t vfr[4];
                ldmx4t(vfr, smV + kt2 * 16 * FSTR + dp * 32 + offQ);
                mma_f16(acc[2 * dp],     pfr, vfr[0], vfr[1]);
                mma_f16(acc[2 * dp + 1], pfr, vfr[2], vfr[3]);
            }
        }
        __syncthreads();
    }

    // epilogue: normalize + plain fp16 into Ah [token, DIM]
    float inv0 = 1.f / l0, inv1 = 1.f / l1;
    int r0 = b * SEQ + m_base + wid * 16 + (lane >> 2);
    int r1 = r0 + 8;
    #pragma unroll
    for (int ntl = 0; ntl < 16; ntl++) {
        int c = h * HD + ntl * 8 + (lane & 3) * 2;
        *(__half2*)(Ah + (size_t)r0 * DIM + c) =
            __floats2half2_rn(acc[ntl][0] * inv0, acc[ntl][1] * inv0);
        *(__half2*)(Ah + (size_t)r1 * DIM + c) =
            __floats2half2_rn(acc[ntl][2] * inv1, acc[ntl][3] * inv1);
    }
}

// ---------------- launch -----------------------------------------------------
extern "C" void kernel_launch(void* const* d_in, const int* in_sizes, int n_in,
                              void* d_out, int out_size)
{
    const float* x  = (const float*)d_in[0];
    const float* fc = (const float*)d_in[1];
    const float* fs = (const float*)d_in[2];
    const float* Wq = (const float*)d_in[3];
    const float* Wk = (const float*)d_in[4];
    const float* Wv = (const float*)d_in[5];
    const float* Wo = (const float*)d_in[6];
    float* out = (float*)d_out;

    __half *Ah, *Wqkv, *Wo2, *Qh, *Kh, *Vh;
    cudaGetSymbolAddress((void**)&Ah,   g_Ah);
    cudaGetSymbolAddress((void**)&Wqkv, g_Wqkv);
    cudaGetSymbolAddress((void**)&Wo2,  g_Wo2);
    cudaGetSymbolAddress((void**)&Qh,   g_Qh);
    cudaGetSymbolAddress((void**)&Kh,   g_Kh);
    cudaGetSymbolAddress((void**)&Vh,   g_Vh);

    cudaFuncSetAttribute((const void*)gemm_h_kernel<0>,
                         cudaFuncAttributeMaxDynamicSharedMemorySize, GSMEM);
    cudaFuncSetAttribute((const void*)gemm_h_kernel<1>,
                         cudaFuncAttributeMaxDynamicSharedMemorySize, GSMEM);
    cudaFuncSetAttribute(flash_mma_kernel, cudaFuncAttributeMaxDynamicSharedMemorySize, FSMEM);

    // conversions
    {
        int n4 = MTOT * DIM / 4;
        cvt_x_kernel<<<(n4 + 255) / 256, 256>>>(x, Ah, n4);
        split_w_kernel<<<dim3(DIM / 32, DIM / 32), dim3(32, 8)>>>(Wq, Wqkv, DIM, DIM, 0);
        split_w_kernel<<<dim3(KVD / 32, DIM / 32), dim3(32, 8)>>>(Wk, Wqkv, DIM, KVD, DIM);
        split_w_kernel<<<dim3(KVD / 32, DIM / 32), dim3(32, 8)>>>(Wv, Wqkv, DIM, KVD, DIM + KVD);
        split_w_kernel<<<dim3(DIM / 32, DIM / 32), dim3(32, 8)>>>(Wo, Wo2, DIM, DIM, 0);
    }

    // fused QKV projection + RoPE + fp16 convert
    gemm_h_kernel<1><<<dim3(NQKV / 128, MTOT / 128), 256, GSMEM>>>(
        Ah, Wqkv, nullptr, 0, fc, fs, Qh, Kh, Vh);

    // flash attention -> Ah fp16
    flash_mma_kernel<<<dim3(SEQ / 64, NH, BATCH), 128, FSMEM>>>(Qh, Kh, Vh, Ah);

    // output projection (hi-only fp16)
    gemm_h_kernel<0><<<dim3(DIM / 128, MTOT / 128), 256, GSMEM>>>(
        Ah, Wo2, out, DIM, nullptr, nullptr, nullptr, nullptr, nullptr);
}